// round 1
// baseline (speedup 1.0000x reference)
#include <cuda_runtime.h>
#include <cuda_bf16.h>
#include <math.h>

// Problem constants
#define BB 2
#define HH 256
#define WW 256
#define NN 65536          // H*W
#define CC 128
#define HEADS 8
#define DH 64             // dim_head
#define GG 64             // SLICE
#define INNER 512         // HEADS*DH
#define SPLITS 64         // split-K for token reduction
#define CHUNK 1024        // tokens per split (NN/SPLITS)

// ---------------- device scratch (static, no allocs) ----------------
__device__ float g_fx[(size_t)BB * NN * INNER];      // fx_mid  [b][n][inner]   256MB
__device__ float g_xm[(size_t)BB * NN * INNER];      // x_mid   [b][n][inner]   256MB
__device__ float g_w [(size_t)BB * HEADS * NN * GG]; // slice_weights [bh][n][g] 256MB
__device__ float g_tokp[(size_t)SPLITS * BB * HEADS * GG * DH]; // partials 16.8MB
__device__ float g_normp[(size_t)SPLITS * BB * HEADS * GG];
__device__ float g_tok [(size_t)BB * HEADS * GG * DH];
__device__ float g_norm[(size_t)BB * HEADS * GG];
__device__ float g_M   [(size_t)BB * HEADS * GG * CC];          // M[bh][g][o]

// ---------------- K1: 3x3 SAME conv as implicit GEMM ----------------
// out[b][n][oc] = sum_{tap,c} x[b][n+off(tap)][c] * W[tap*128+c][oc] + bias[oc]
// Tile: 64 pixels (one image row segment) x 64 out-channels, K-chunk 32.
__global__ void conv3x3_kernel(const float* __restrict__ x,
                               const float* __restrict__ W,
                               const float* __restrict__ bias,
                               float* __restrict__ out) {
    const int b   = blockIdx.z;
    const int oc0 = blockIdx.y * 64;
    const int n0  = blockIdx.x * 64;
    const int hrow = n0 >> 8;        // 64 | 256 -> tile stays in one image row
    const int w0   = n0 & 255;
    const int tx = threadIdx.x, ty = threadIdx.y;
    const int tid = ty * 16 + tx;

    __shared__ float As[64][32];
    __shared__ float Bs[32][64];

    float acc[4][4] = {};

    for (int kg0 = 0; kg0 < 9 * CC; kg0 += 32) {
        const int tap = kg0 >> 7;            // 4 chunks of 32 per tap
        const int dy = tap / 3 - 1, dx = tap % 3 - 1;
        const int c0 = kg0 & 127;
        const int hp = hrow + dy;
        const bool hok = (hp >= 0) && (hp < HH);

        #pragma unroll
        for (int e = 0; e < 8; e++) {
            int idx = tid + e * 256;
            int m = idx >> 5, k = idx & 31;
            int wp = w0 + m + dx;
            float v = 0.f;
            if (hok && wp >= 0 && wp < WW)
                v = x[((size_t)b * NN + (size_t)hp * WW + wp) * CC + c0 + k];
            As[m][k] = v;
        }
        #pragma unroll
        for (int e = 0; e < 8; e++) {
            int idx = tid + e * 256;
            int k = idx >> 6, j = idx & 63;
            Bs[k][j] = W[(size_t)(kg0 + k) * INNER + oc0 + j];
        }
        __syncthreads();

        #pragma unroll
        for (int kk = 0; kk < 32; kk++) {
            float a[4], bv[4];
            #pragma unroll
            for (int i = 0; i < 4; i++) a[i] = As[ty + 16 * i][kk];
            #pragma unroll
            for (int j = 0; j < 4; j++) bv[j] = Bs[kk][tx + 16 * j];
            #pragma unroll
            for (int i = 0; i < 4; i++)
                #pragma unroll
                for (int j = 0; j < 4; j++)
                    acc[i][j] += a[i] * bv[j];
        }
        __syncthreads();
    }

    #pragma unroll
    for (int i = 0; i < 4; i++) {
        int n = n0 + ty + 16 * i;
        #pragma unroll
        for (int j = 0; j < 4; j++) {
            int oc = oc0 + tx + 16 * j;
            out[((size_t)b * NN + n) * INNER + oc] = acc[i][j] + bias[oc];
        }
    }
}

// ---------------- K2: slice logits + softmax -> g_w ----------------
// logits[n][g] = (x_mid[n]·Wslice[g] + bslice[g]) / clamp(temp_h, .1, 5); softmax over g.
__global__ void logits_softmax_kernel(const float* __restrict__ xm,
                                      const float* __restrict__ Wslice,
                                      const float* __restrict__ bslice,
                                      const float* __restrict__ temperature,
                                      float* __restrict__ wout) {
    const int bh = blockIdx.y;           // b*8+h
    const int b = bh >> 3, h = bh & 7;
    const int n0 = blockIdx.x * 64;
    const int tx = threadIdx.x, ty = threadIdx.y;
    const int tid = ty * 16 + tx;

    __shared__ float Xs[64][65];
    __shared__ float Ws[64][65];

    #pragma unroll
    for (int e = 0; e < 16; e++) {
        int idx = tid + e * 256;
        int m = idx >> 6, d = idx & 63;
        Xs[m][d] = xm[((size_t)b * NN + n0 + m) * INNER + h * DH + d];
        Ws[m][d] = Wslice[idx];          // [g][d] row-major
    }
    __syncthreads();

    float acc[4][4] = {};
    #pragma unroll
    for (int kk = 0; kk < 64; kk++) {
        float a[4], bv[4];
        #pragma unroll
        for (int i = 0; i < 4; i++) a[i] = Xs[ty + 16 * i][kk];
        #pragma unroll
        for (int j = 0; j < 4; j++) bv[j] = Ws[tx + 16 * j][kk];
        #pragma unroll
        for (int i = 0; i < 4; i++)
            #pragma unroll
            for (int j = 0; j < 4; j++)
                acc[i][j] += a[i] * bv[j];
    }

    float temp = temperature[h];
    temp = fminf(fmaxf(temp, 0.1f), 5.0f);
    const float inv_t = 1.0f / temp;

    #pragma unroll
    for (int j = 0; j < 4; j++) {
        float bs = bslice[tx + 16 * j];
        #pragma unroll
        for (int i = 0; i < 4; i++)
            acc[i][j] = (acc[i][j] + bs) * inv_t;
    }

    // row softmax across tx (16 lanes per half-warp, width-16 shuffles)
    #pragma unroll
    for (int i = 0; i < 4; i++) {
        float mx = acc[i][0];
        #pragma unroll
        for (int j = 1; j < 4; j++) mx = fmaxf(mx, acc[i][j]);
        #pragma unroll
        for (int o = 1; o < 16; o <<= 1)
            mx = fmaxf(mx, __shfl_xor_sync(0xffffffffu, mx, o, 16));
        float s = 0.f;
        #pragma unroll
        for (int j = 0; j < 4; j++) { acc[i][j] = __expf(acc[i][j] - mx); s += acc[i][j]; }
        #pragma unroll
        for (int o = 1; o < 16; o <<= 1)
            s += __shfl_xor_sync(0xffffffffu, s, o, 16);
        float inv = 1.0f / s;
        int n = n0 + ty + 16 * i;
        #pragma unroll
        for (int j = 0; j < 4; j++)
            wout[((size_t)bh * NN + n) * GG + tx + 16 * j] = acc[i][j] * inv;
    }
}

// ---------------- K3: split-K reduction: slice_token partials ----------------
// tokp[s][bh][g][d] = sum_{n in chunk s} w[n][g] * fx[n][d] ; normp = sum w
__global__ void token_reduce_kernel(const float* __restrict__ wts,
                                    const float* __restrict__ fx,
                                    float* __restrict__ tokp,
                                    float* __restrict__ normp) {
    const int bh = blockIdx.y;
    const int b = bh >> 3, h = bh & 7;
    const int split = blockIdx.x;
    const int nbase = split * CHUNK;
    const int tx = threadIdx.x, ty = threadIdx.y;
    const int tid = ty * 16 + tx;

    __shared__ float wb[8][64];
    __shared__ float fb[8][64];

    float acc[4][4] = {};
    float nacc[4] = {};

    for (int t0 = 0; t0 < CHUNK; t0 += 8) {
        #pragma unroll
        for (int e = 0; e < 2; e++) {
            int idx = tid + e * 256;
            int t = idx >> 6, q = idx & 63;
            int n = nbase + t0 + t;
            wb[t][q] = wts[((size_t)bh * NN + n) * GG + q];
            fb[t][q] = fx[((size_t)b * NN + n) * INNER + h * DH + q];
        }
        __syncthreads();
        #pragma unroll
        for (int t = 0; t < 8; t++) {
            float a[4], bv[4];
            #pragma unroll
            for (int i = 0; i < 4; i++) a[i] = wb[t][ty + 16 * i];
            #pragma unroll
            for (int j = 0; j < 4; j++) bv[j] = fb[t][tx + 16 * j];
            #pragma unroll
            for (int i = 0; i < 4; i++)
                #pragma unroll
                for (int j = 0; j < 4; j++)
                    acc[i][j] += a[i] * bv[j];
            if (tx == 0) {
                #pragma unroll
                for (int i = 0; i < 4; i++) nacc[i] += a[i];
            }
        }
        __syncthreads();
    }

    const size_t base = ((size_t)split * (BB * HEADS) + bh) * (GG * DH);
    #pragma unroll
    for (int i = 0; i < 4; i++)
        #pragma unroll
        for (int j = 0; j < 4; j++)
            tokp[base + (size_t)(ty + 16 * i) * DH + tx + 16 * j] = acc[i][j];
    if (tx == 0) {
        #pragma unroll
        for (int i = 0; i < 4; i++)
            normp[((size_t)split * (BB * HEADS) + bh) * GG + ty + 16 * i] = nacc[i];
    }
}

// ---------------- K3b: deterministic split reduction ----------------
__global__ void split_reduce_kernel(const float* __restrict__ tokp,
                                    const float* __restrict__ normp,
                                    float* __restrict__ tok,
                                    float* __restrict__ norm) {
    const int blk = blockIdx.x;
    const int tid = threadIdx.x;
    if (blk < 256) {                      // 256*256 = 65536 tok elements
        int idx = blk * 256 + tid;
        float s = 0.f;
        #pragma unroll 8
        for (int sp = 0; sp < SPLITS; sp++)
            s += tokp[(size_t)sp * 65536 + idx];
        tok[idx] = s;
    } else {                              // 4 blocks * 256 = 1024 norm elements
        int idx = (blk - 256) * 256 + tid;
        float s = 0.f;
        #pragma unroll 8
        for (int sp = 0; sp < SPLITS; sp++)
            s += normp[(size_t)sp * 1024 + idx];
        norm[idx] = s;
    }
}

// ---------------- K4: tiny attention per (b,h) + fused M = out_slice·Woutᵀ ----------------
__global__ void attn_kernel(const float* __restrict__ tok,
                            const float* __restrict__ norm,
                            const float* __restrict__ Wq,
                            const float* __restrict__ Wk,
                            const float* __restrict__ Wv,
                            const float* __restrict__ Wout,
                            float* __restrict__ Mout) {
    const int bh = blockIdx.x;
    const int h = bh & 7;
    const int tx = threadIdx.x, ty = threadIdx.y;
    const int tid = ty * 16 + tx;

    __shared__ float A[64][65];   // st -> attn
    __shared__ float Bm[64][65];  // q  -> st(reload) -> out_slice
    __shared__ float Cm[64][65];  // k  -> v

    // 1. load slice tokens (normalized)
    #pragma unroll
    for (int e = 0; e < 16; e++) {
        int idx = tid + e * 256;
        int g = idx >> 6, d = idx & 63;
        A[g][d] = tok[(size_t)bh * 4096 + idx] / (norm[bh * 64 + g] + 1e-5f);
    }
    __syncthreads();

    // 2. q -> Bm ; k -> Cm      (q[g][e] = sum_d st[g][d]*Wq[e][d])
    {
        float aq[4][4] = {}, ak[4][4] = {};
        #pragma unroll
        for (int kk = 0; kk < 64; kk++) {
            float a[4];
            #pragma unroll
            for (int i = 0; i < 4; i++) a[i] = A[ty + 16 * i][kk];
            #pragma unroll
            for (int j = 0; j < 4; j++) {
                float wq = __ldg(&Wq[(tx + 16 * j) * 64 + kk]);
                float wk = __ldg(&Wk[(tx + 16 * j) * 64 + kk]);
                #pragma unroll
                for (int i = 0; i < 4; i++) {
                    aq[i][j] += a[i] * wq;
                    ak[i][j] += a[i] * wk;
                }
            }
        }
        #pragma unroll
        for (int i = 0; i < 4; i++)
            #pragma unroll
            for (int j = 0; j < 4; j++) {
                Bm[ty + 16 * i][tx + 16 * j] = aq[i][j];
                Cm[ty + 16 * i][tx + 16 * j] = ak[i][j];
            }
    }
    __syncthreads();

    // 3. attn = softmax(q kᵀ * SCALE) -> A
    {
        float L[4][4] = {};
        #pragma unroll
        for (int kk = 0; kk < 64; kk++) {
            float a[4], bv[4];
            #pragma unroll
            for (int i = 0; i < 4; i++) a[i] = Bm[ty + 16 * i][kk];
            #pragma unroll
            for (int j = 0; j < 4; j++) bv[j] = Cm[tx + 16 * j][kk];
            #pragma unroll
            for (int i = 0; i < 4; i++)
                #pragma unroll
                for (int j = 0; j < 4; j++)
                    L[i][j] += a[i] * bv[j];
        }
        #pragma unroll
        for (int i = 0; i < 4; i++) {
            #pragma unroll
            for (int j = 0; j < 4; j++) L[i][j] *= 0.125f;   // SCALE = 64^-0.5
            float mx = L[i][0];
            #pragma unroll
            for (int j = 1; j < 4; j++) mx = fmaxf(mx, L[i][j]);
            #pragma unroll
            for (int o = 1; o < 16; o <<= 1)
                mx = fmaxf(mx, __shfl_xor_sync(0xffffffffu, mx, o, 16));
            float s = 0.f;
            #pragma unroll
            for (int j = 0; j < 4; j++) { L[i][j] = __expf(L[i][j] - mx); s += L[i][j]; }
            #pragma unroll
            for (int o = 1; o < 16; o <<= 1)
                s += __shfl_xor_sync(0xffffffffu, s, o, 16);
            float inv = 1.0f / s;
            #pragma unroll
            for (int j = 0; j < 4; j++)
                A[ty + 16 * i][tx + 16 * j] = L[i][j] * inv;
        }
    }
    __syncthreads();

    // 4. reload st -> Bm
    #pragma unroll
    for (int e = 0; e < 16; e++) {
        int idx = tid + e * 256;
        int g = idx >> 6;
        Bm[g][idx & 63] = tok[(size_t)bh * 4096 + idx] / (norm[bh * 64 + g] + 1e-5f);
    }
    __syncthreads();

    // 5. v -> Cm
    {
        float av[4][4] = {};
        #pragma unroll
        for (int kk = 0; kk < 64; kk++) {
            float a[4];
            #pragma unroll
            for (int i = 0; i < 4; i++) a[i] = Bm[ty + 16 * i][kk];
            #pragma unroll
            for (int j = 0; j < 4; j++) {
                float wv = __ldg(&Wv[(tx + 16 * j) * 64 + kk]);
                #pragma unroll
                for (int i = 0; i < 4; i++) av[i][j] += a[i] * wv;
            }
        }
        __syncthreads();
        #pragma unroll
        for (int i = 0; i < 4; i++)
            #pragma unroll
            for (int j = 0; j < 4; j++)
                Cm[ty + 16 * i][tx + 16 * j] = av[i][j];
    }
    __syncthreads();

    // 6. out_slice = attn·v -> Bm
    {
        float ao[4][4] = {};
        #pragma unroll
        for (int kk = 0; kk < 64; kk++) {
            float a[4], bv[4];
            #pragma unroll
            for (int i = 0; i < 4; i++) a[i] = A[ty + 16 * i][kk];
            #pragma unroll
            for (int j = 0; j < 4; j++) bv[j] = Cm[kk][tx + 16 * j];
            #pragma unroll
            for (int i = 0; i < 4; i++)
                #pragma unroll
                for (int j = 0; j < 4; j++)
                    ao[i][j] += a[i] * bv[j];
        }
        __syncthreads();
        #pragma unroll
        for (int i = 0; i < 4; i++)
            #pragma unroll
            for (int j = 0; j < 4; j++)
                Bm[ty + 16 * i][tx + 16 * j] = ao[i][j];
    }
    __syncthreads();

    // 7. M[g][o] = sum_d out_slice[g][d]*Wout[o][h*64+d]   (o in 0..127)
    {
        float am[4][8] = {};
        #pragma unroll
        for (int kk = 0; kk < 64; kk++) {
            float a[4];
            #pragma unroll
            for (int i = 0; i < 4; i++) a[i] = Bm[ty + 16 * i][kk];
            #pragma unroll
            for (int j = 0; j < 8; j++) {
                float wv = __ldg(&Wout[(size_t)(tx + 16 * j) * INNER + h * DH + kk]);
                #pragma unroll
                for (int i = 0; i < 4; i++) am[i][j] += a[i] * wv;
            }
        }
        #pragma unroll
        for (int i = 0; i < 4; i++)
            #pragma unroll
            for (int j = 0; j < 8; j++)
                Mout[((size_t)bh * GG + ty + 16 * i) * CC + tx + 16 * j] = am[i][j];
    }
}

// ---------------- K5: fused scatter + output projection ----------------
// out[b][n][o] = bout[o] + sum_{h,g} w[bh][n][g] * M[bh][g][o]
__global__ void final_kernel(const float* __restrict__ wts,
                             const float* __restrict__ M,
                             const float* __restrict__ bout,
                             float* __restrict__ out) {
    const int b = blockIdx.y;
    const int n0 = blockIdx.x * 64;
    const int tx = threadIdx.x, ty = threadIdx.y;
    const int tid = ty * 16 + tx;

    __shared__ float As[64][17];
    __shared__ float Bs[16][128];

    float acc[4][8] = {};

    for (int h = 0; h < HEADS; h++) {
        const int bh = b * HEADS + h;
        for (int g0 = 0; g0 < GG; g0 += 16) {
            #pragma unroll
            for (int e = 0; e < 4; e++) {
                int idx = tid + e * 256;
                int m = idx >> 4, g = idx & 15;
                As[m][g] = wts[((size_t)bh * NN + n0 + m) * GG + g0 + g];
            }
            #pragma unroll
            for (int e = 0; e < 8; e++) {
                int idx = tid + e * 256;
                int k = idx >> 7, o = idx & 127;
                Bs[k][o] = M[((size_t)bh * GG + g0 + k) * CC + o];
            }
            __syncthreads();
            #pragma unroll
            for (int kk = 0; kk < 16; kk++) {
                float a[4], bv[8];
                #pragma unroll
                for (int i = 0; i < 4; i++) a[i] = As[ty + 16 * i][kk];
                #pragma unroll
                for (int j = 0; j < 8; j++) bv[j] = Bs[kk][tx + 16 * j];
                #pragma unroll
                for (int i = 0; i < 4; i++)
                    #pragma unroll
                    for (int j = 0; j < 8; j++)
                        acc[i][j] += a[i] * bv[j];
            }
            __syncthreads();
        }
    }

    #pragma unroll
    for (int i = 0; i < 4; i++) {
        int n = n0 + ty + 16 * i;
        #pragma unroll
        for (int j = 0; j < 8; j++) {
            int o = tx + 16 * j;
            out[((size_t)b * NN + n) * CC + o] = acc[i][j] + bout[o];
        }
    }
}

// ---------------- launch ----------------
extern "C" void kernel_launch(void* const* d_in, const int* in_sizes, int n_in,
                              void* d_out, int out_size) {
    const float* x     = (const float*)d_in[0];
    const float* Wfx   = (const float*)d_in[1];
    const float* bfx   = (const float*)d_in[2];
    const float* Wx    = (const float*)d_in[3];
    const float* bx    = (const float*)d_in[4];
    const float* Wsl   = (const float*)d_in[5];
    const float* bsl   = (const float*)d_in[6];
    const float* temp  = (const float*)d_in[7];
    const float* Wq    = (const float*)d_in[8];
    const float* Wk    = (const float*)d_in[9];
    const float* Wv    = (const float*)d_in[10];
    const float* Wout  = (const float*)d_in[11];
    const float* bout  = (const float*)d_in[12];
    float* out = (float*)d_out;

    float *p_fx, *p_xm, *p_w, *p_tokp, *p_normp, *p_tok, *p_norm, *p_M;
    cudaGetSymbolAddress((void**)&p_fx, g_fx);
    cudaGetSymbolAddress((void**)&p_xm, g_xm);
    cudaGetSymbolAddress((void**)&p_w, g_w);
    cudaGetSymbolAddress((void**)&p_tokp, g_tokp);
    cudaGetSymbolAddress((void**)&p_normp, g_normp);
    cudaGetSymbolAddress((void**)&p_tok, g_tok);
    cudaGetSymbolAddress((void**)&p_norm, g_norm);
    cudaGetSymbolAddress((void**)&p_M, g_M);

    dim3 blk(16, 16);

    // 1+2. two convs
    conv3x3_kernel<<<dim3(NN / 64, INNER / 64, BB), blk>>>(x, Wfx, bfx, p_fx);
    conv3x3_kernel<<<dim3(NN / 64, INNER / 64, BB), blk>>>(x, Wx,  bx,  p_xm);

    // 3. logits + softmax -> slice weights
    logits_softmax_kernel<<<dim3(NN / 64, BB * HEADS), blk>>>(p_xm, Wsl, bsl, temp, p_w);

    // 4. slice token split-K partials + reduce
    token_reduce_kernel<<<dim3(SPLITS, BB * HEADS), blk>>>(p_w, p_fx, p_tokp, p_normp);
    split_reduce_kernel<<<260, 256>>>(p_tokp, p_normp, p_tok, p_norm);

    // 5. tiny attention + fused Wout fold
    attn_kernel<<<BB * HEADS, blk>>>(p_tok, p_norm, Wq, Wk, Wv, Wout, p_M);

    // 6. fused scatter + projection
    final_kernel<<<dim3(NN / 64, BB), blk>>>(p_w, p_M, bout, out);
}

// round 2
// speedup vs baseline: 2.3027x; 2.3027x over previous
#include <cuda_runtime.h>
#include <cuda_bf16.h>
#include <math.h>
#include <stdint.h>

// Problem constants
#define BB 2
#define HH 256
#define WW 256
#define NN 65536          // H*W
#define CC 128
#define HEADS 8
#define DH 64             // dim_head
#define GG 64             // SLICE
#define INNER 512         // HEADS*DH
#define SPLITS 64         // split-K for token reduction
#define CHUNK 1024        // tokens per split (NN/SPLITS)
#define KTOT 1152         // 9 taps * 128 channels

// ---------------- device scratch (static, no allocs) ----------------
__device__ float g_fx[(size_t)BB * NN * INNER];      // fx_mid  [b][n][inner]
__device__ float g_xm[(size_t)BB * NN * INNER];      // x_mid   [b][n][inner]
__device__ float g_w [(size_t)BB * HEADS * NN * GG]; // slice_weights [bh][n][g]
__device__ float g_tokp[(size_t)SPLITS * BB * HEADS * GG * DH];
__device__ float g_normp[(size_t)SPLITS * BB * HEADS * GG];
__device__ float g_tok [(size_t)BB * HEADS * GG * DH];
__device__ float g_norm[(size_t)BB * HEADS * GG];
__device__ float g_M   [(size_t)BB * HEADS * GG * CC];

// bf16 3-split staging
__device__ __nv_bfloat16 g_xhi[(size_t)BB * NN * CC];
__device__ __nv_bfloat16 g_xlo[(size_t)BB * NN * CC];
__device__ __nv_bfloat16 g_whi[(size_t)1024 * KTOT];  // [oc' 0..1023][k] transposed
__device__ __nv_bfloat16 g_wlo[(size_t)1024 * KTOT];

// ---------------- prep: split fp32 -> bf16 hi + bf16 lo ----------------
__global__ void split_x_kernel(const float* __restrict__ x,
                               __nv_bfloat16* __restrict__ xhi,
                               __nv_bfloat16* __restrict__ xlo) {
    size_t i = (size_t)blockIdx.x * 256 + threadIdx.x;   // total BB*NN*CC = 16,777,216
    float f = x[i];
    __nv_bfloat16 h = __float2bfloat16(f);
    float r = f - __bfloat162float(h);
    xhi[i] = h;
    xlo[i] = __float2bfloat16(r);
}

__global__ void split_w_kernel(const float* __restrict__ Wfx,
                               const float* __restrict__ Wx,
                               __nv_bfloat16* __restrict__ whi,
                               __nv_bfloat16* __restrict__ wlo) {
    int i = blockIdx.x * 256 + threadIdx.x;              // total 1024*1152
    int oc = i / KTOT;
    int k  = i - oc * KTOT;
    float f = (oc < 512) ? Wfx[(size_t)k * 512 + oc]
                         : Wx [(size_t)k * 512 + oc - 512];
    __nv_bfloat16 h = __float2bfloat16(f);
    float r = f - __bfloat162float(h);
    whi[i] = h;
    wlo[i] = __float2bfloat16(r);
}

// ---------------- conv as implicit GEMM on tensor cores ----------------
// Block: 128 pixels x 128 oc, K=1152 chunked by 32, 2-stage cp.async.
// 8 warps: warp_m = wid&1 (64 rows each), warp_n = wid>>1 (32 cols each).
// 3xBF16 split: acc += Ahi*Bhi + Ahi*Blo + Alo*Bhi (fp32 accumulate).

__device__ __forceinline__ void cp16(uint32_t saddr, const void* g, bool valid) {
    int sz = valid ? 16 : 0;
    asm volatile("cp.async.cg.shared.global [%0], [%1], 16, %2;\n"
                 :: "r"(saddr), "l"(g), "r"(sz));
}

__device__ __forceinline__ uint32_t lds_frag(const uint32_t* base, int row, int kw) {
    // physical word layout: row*16 + ((kw>>2)^(row&3))*4 + (kw&3)
    return base[row * 16 + ((((kw >> 2) ^ (row & 3)) << 2) | (kw & 3))];
}

__device__ __forceinline__ void mma_bf16(float c[4], uint32_t a0, uint32_t a1,
                                         uint32_t a2, uint32_t a3,
                                         uint32_t b0, uint32_t b1) {
    asm volatile(
        "mma.sync.aligned.m16n8k16.row.col.f32.bf16.bf16.f32 "
        "{%0,%1,%2,%3}, {%4,%5,%6,%7}, {%8,%9}, {%0,%1,%2,%3};"
        : "+f"(c[0]), "+f"(c[1]), "+f"(c[2]), "+f"(c[3])
        : "r"(a0), "r"(a1), "r"(a2), "r"(a3), "r"(b0), "r"(b1));
}

// Issue one k-chunk (kc=32) worth of cp.asyncs into stage buffer.
__device__ __forceinline__ void load_tile(
    uint32_t sbase_bytes,
    const __nv_bfloat16* __restrict__ Xhi, const __nv_bfloat16* __restrict__ Xlo,
    const __nv_bfloat16* __restrict__ Whi, const __nv_bfloat16* __restrict__ Wlo,
    int it, int b, int hrow, int w0, int ocb, int tid)
{
    const int kg  = it * 32;
    const int tap = kg >> 7;
    const int dy = tap / 3 - 1, dx = tap % 3 - 1;
    const int c0 = kg & 127;
    const int hp = hrow + dy;
    const bool hok = (hp >= 0) && (hp < HH);

    #pragma unroll
    for (int j = 0; j < 8; j++) {
        int id  = tid + j * 256;        // 0..2047
        int arr = id >> 9;              // 0:Ahi 1:Alo 2:Bhi 3:Blo
        int c   = id & 511;
        int row = c >> 2;
        int c4  = c & 3;
        uint32_t woff = (uint32_t)row * 16 + ((c4 ^ (row & 3)) << 2);
        uint32_t saddr = sbase_bytes + (arr * 2048 + woff) * 4;
        const __nv_bfloat16* g;
        bool valid;
        if (arr < 2) {
            int wp = w0 + row + dx;
            valid = hok && (wp >= 0) && (wp < WW);
            int wpc = valid ? wp : 0;
            int hpc = (hok) ? hp : 0;
            size_t off = (((size_t)b * NN + (size_t)hpc * WW + wpc) * CC + c0 + c4 * 8);
            g = (arr == 0 ? Xhi : Xlo) + off;
        } else {
            int ocr = ocb * 128 + row;
            size_t off = (size_t)ocr * KTOT + kg + c4 * 8;
            g = (arr == 2 ? Whi : Wlo) + off;
            valid = true;
        }
        cp16(saddr, g, valid);
    }
}

__global__ __launch_bounds__(256, 1)
void conv_mma_kernel(const __nv_bfloat16* __restrict__ Xhi,
                     const __nv_bfloat16* __restrict__ Xlo,
                     const __nv_bfloat16* __restrict__ Whi,
                     const __nv_bfloat16* __restrict__ Wlo,
                     const float* __restrict__ bfx,
                     const float* __restrict__ bx,
                     float* __restrict__ ofx,
                     float* __restrict__ oxm)
{
    extern __shared__ uint32_t smem_u32[];   // 2 stages * 4 arrays * 2048 words

    const int ocb = blockIdx.x;              // 0..7 (oc' tile of 128)
    const int pt  = blockIdx.y;              // 0..511 pixel tile
    const int b   = blockIdx.z;
    const int n0  = pt * 128;
    const int hrow = n0 >> 8;
    const int w0   = n0 & 255;

    const int tid  = threadIdx.x;
    const int wid  = tid >> 5;
    const int lane = tid & 31;
    const int grp  = lane >> 2;
    const int tid4 = lane & 3;
    const int wm   = wid & 1;
    const int wn   = wid >> 1;

    float acc[4][4][4];
    #pragma unroll
    for (int i = 0; i < 4; i++)
        #pragma unroll
        for (int j = 0; j < 4; j++)
            #pragma unroll
            for (int r = 0; r < 4; r++) acc[i][j][r] = 0.f;

    uint32_t sbase = (uint32_t)__cvta_generic_to_shared(smem_u32);

    load_tile(sbase, Xhi, Xlo, Whi, Wlo, 0, b, hrow, w0, ocb, tid);
    asm volatile("cp.async.commit_group;\n" ::: "memory");

    for (int it = 0; it < 36; ++it) {
        const int cur = it & 1;
        if (it + 1 < 36) {
            load_tile(sbase + (uint32_t)(1 - cur) * 32768,
                      Xhi, Xlo, Whi, Wlo, it + 1, b, hrow, w0, ocb, tid);
            asm volatile("cp.async.commit_group;\n" ::: "memory");
            asm volatile("cp.async.wait_group 1;\n" ::: "memory");
        } else {
            asm volatile("cp.async.wait_group 0;\n" ::: "memory");
        }
        __syncthreads();

        const uint32_t* Ahi = smem_u32 + (size_t)cur * 8192;
        const uint32_t* Alo = Ahi + 2048;
        const uint32_t* Bhi = Ahi + 4096;
        const uint32_t* Blo = Ahi + 6144;

        #pragma unroll
        for (int s = 0; s < 2; s++) {
            const int kwb = s * 8;
            uint32_t ah[4][4], al[4][4];
            #pragma unroll
            for (int mi = 0; mi < 4; mi++) {
                int r0 = wm * 64 + mi * 16 + grp;
                ah[mi][0] = lds_frag(Ahi, r0,     kwb + tid4);
                ah[mi][1] = lds_frag(Ahi, r0 + 8, kwb + tid4);
                ah[mi][2] = lds_frag(Ahi, r0,     kwb + tid4 + 4);
                ah[mi][3] = lds_frag(Ahi, r0 + 8, kwb + tid4 + 4);
                al[mi][0] = lds_frag(Alo, r0,     kwb + tid4);
                al[mi][1] = lds_frag(Alo, r0 + 8, kwb + tid4);
                al[mi][2] = lds_frag(Alo, r0,     kwb + tid4 + 4);
                al[mi][3] = lds_frag(Alo, r0 + 8, kwb + tid4 + 4);
            }
            uint32_t bh[4][2], bl[4][2];
            #pragma unroll
            for (int ni = 0; ni < 4; ni++) {
                int r0 = wn * 32 + ni * 8 + grp;
                bh[ni][0] = lds_frag(Bhi, r0, kwb + tid4);
                bh[ni][1] = lds_frag(Bhi, r0, kwb + tid4 + 4);
                bl[ni][0] = lds_frag(Blo, r0, kwb + tid4);
                bl[ni][1] = lds_frag(Blo, r0, kwb + tid4 + 4);
            }
            #pragma unroll
            for (int mi = 0; mi < 4; mi++)
                #pragma unroll
                for (int ni = 0; ni < 4; ni++) {
                    mma_bf16(acc[mi][ni], ah[mi][0], ah[mi][1], ah[mi][2], ah[mi][3],
                             bh[ni][0], bh[ni][1]);
                    mma_bf16(acc[mi][ni], ah[mi][0], ah[mi][1], ah[mi][2], ah[mi][3],
                             bl[ni][0], bl[ni][1]);
                    mma_bf16(acc[mi][ni], al[mi][0], al[mi][1], al[mi][2], al[mi][3],
                             bh[ni][0], bh[ni][1]);
                }
        }
        __syncthreads();
    }

    // epilogue
    const bool is_fx = (ocb < 4);
    float* outp = is_fx ? ofx : oxm;
    const float* biasp = is_fx ? bfx : bx;
    const int ocbase = (ocb & 3) * 128;   // within its 512-wide output

    #pragma unroll
    for (int mi = 0; mi < 4; mi++) {
        int row = wm * 64 + mi * 16 + grp;
        int n  = n0 + row;
        #pragma unroll
        for (int ni = 0; ni < 4; ni++) {
            int col = wn * 32 + ni * 8 + tid4 * 2;
            int oc  = ocbase + col;
            float b0v = biasp[oc], b1v = biasp[oc + 1];
            size_t base0 = ((size_t)b * NN + n) * INNER + oc;
            outp[base0]     = acc[mi][ni][0] + b0v;
            outp[base0 + 1] = acc[mi][ni][1] + b1v;
            size_t base1 = ((size_t)b * NN + n + 8) * INNER + oc;
            outp[base1]     = acc[mi][ni][2] + b0v;
            outp[base1 + 1] = acc[mi][ni][3] + b1v;
        }
    }
}

// ---------------- K2: slice logits + softmax -> g_w ----------------
__global__ void logits_softmax_kernel(const float* __restrict__ xm,
                                      const float* __restrict__ Wslice,
                                      const float* __restrict__ bslice,
                                      const float* __restrict__ temperature,
                                      float* __restrict__ wout) {
    const int bh = blockIdx.y;           // b*8+h
    const int b = bh >> 3, h = bh & 7;
    const int n0 = blockIdx.x * 64;
    const int tx = threadIdx.x, ty = threadIdx.y;
    const int tid = ty * 16 + tx;

    __shared__ float Xs[64][65];
    __shared__ float Ws[64][65];

    #pragma unroll
    for (int e = 0; e < 16; e++) {
        int idx = tid + e * 256;
        int m = idx >> 6, d = idx & 63;
        Xs[m][d] = xm[((size_t)b * NN + n0 + m) * INNER + h * DH + d];
        Ws[m][d] = Wslice[idx];          // [g][d] row-major
    }
    __syncthreads();

    float acc[4][4] = {};
    #pragma unroll
    for (int kk = 0; kk < 64; kk++) {
        float a[4], bv[4];
        #pragma unroll
        for (int i = 0; i < 4; i++) a[i] = Xs[ty + 16 * i][kk];
        #pragma unroll
        for (int j = 0; j < 4; j++) bv[j] = Ws[tx + 16 * j][kk];
        #pragma unroll
        for (int i = 0; i < 4; i++)
            #pragma unroll
            for (int j = 0; j < 4; j++)
                acc[i][j] += a[i] * bv[j];
    }

    float temp = temperature[h];
    temp = fminf(fmaxf(temp, 0.1f), 5.0f);
    const float inv_t = 1.0f / temp;

    #pragma unroll
    for (int j = 0; j < 4; j++) {
        float bs = bslice[tx + 16 * j];
        #pragma unroll
        for (int i = 0; i < 4; i++)
            acc[i][j] = (acc[i][j] + bs) * inv_t;
    }

    #pragma unroll
    for (int i = 0; i < 4; i++) {
        float mx = acc[i][0];
        #pragma unroll
        for (int j = 1; j < 4; j++) mx = fmaxf(mx, acc[i][j]);
        #pragma unroll
        for (int o = 1; o < 16; o <<= 1)
            mx = fmaxf(mx, __shfl_xor_sync(0xffffffffu, mx, o, 16));
        float s = 0.f;
        #pragma unroll
        for (int j = 0; j < 4; j++) { acc[i][j] = __expf(acc[i][j] - mx); s += acc[i][j]; }
        #pragma unroll
        for (int o = 1; o < 16; o <<= 1)
            s += __shfl_xor_sync(0xffffffffu, s, o, 16);
        float inv = 1.0f / s;
        int n = n0 + ty + 16 * i;
        #pragma unroll
        for (int j = 0; j < 4; j++)
            wout[((size_t)bh * NN + n) * GG + tx + 16 * j] = acc[i][j] * inv;
    }
}

// ---------------- K3: split-K reduction: slice_token partials ----------------
__global__ void token_reduce_kernel(const float* __restrict__ wts,
                                    const float* __restrict__ fx,
                                    float* __restrict__ tokp,
                                    float* __restrict__ normp) {
    const int bh = blockIdx.y;
    const int b = bh >> 3, h = bh & 7;
    const int split = blockIdx.x;
    const int nbase = split * CHUNK;
    const int tx = threadIdx.x, ty = threadIdx.y;
    const int tid = ty * 16 + tx;

    __shared__ float wb[8][64];
    __shared__ float fb[8][64];

    float acc[4][4] = {};
    float nacc[4] = {};

    for (int t0 = 0; t0 < CHUNK; t0 += 8) {
        #pragma unroll
        for (int e = 0; e < 2; e++) {
            int idx = tid + e * 256;
            int t = idx >> 6, q = idx & 63;
            int n = nbase + t0 + t;
            wb[t][q] = wts[((size_t)bh * NN + n) * GG + q];
            fb[t][q] = fx[((size_t)b * NN + n) * INNER + h * DH + q];
        }
        __syncthreads();
        #pragma unroll
        for (int t = 0; t < 8; t++) {
            float a[4], bv[4];
            #pragma unroll
            for (int i = 0; i < 4; i++) a[i] = wb[t][ty + 16 * i];
            #pragma unroll
            for (int j = 0; j < 4; j++) bv[j] = fb[t][tx + 16 * j];
            #pragma unroll
            for (int i = 0; i < 4; i++)
                #pragma unroll
                for (int j = 0; j < 4; j++)
                    acc[i][j] += a[i] * bv[j];
            if (tx == 0) {
                #pragma unroll
                for (int i = 0; i < 4; i++) nacc[i] += a[i];
            }
        }
        __syncthreads();
    }

    const size_t base = ((size_t)split * (BB * HEADS) + bh) * (GG * DH);
    #pragma unroll
    for (int i = 0; i < 4; i++)
        #pragma unroll
        for (int j = 0; j < 4; j++)
            tokp[base + (size_t)(ty + 16 * i) * DH + tx + 16 * j] = acc[i][j];
    if (tx == 0) {
        #pragma unroll
        for (int i = 0; i < 4; i++)
            normp[((size_t)split * (BB * HEADS) + bh) * GG + ty + 16 * i] = nacc[i];
    }
}

// ---------------- K3b: deterministic split reduction ----------------
__global__ void split_reduce_kernel(const float* __restrict__ tokp,
                                    const float* __restrict__ normp,
                                    float* __restrict__ tok,
                                    float* __restrict__ norm) {
    const int blk = blockIdx.x;
    const int tid = threadIdx.x;
    if (blk < 256) {
        int idx = blk * 256 + tid;
        float s = 0.f;
        #pragma unroll 8
        for (int sp = 0; sp < SPLITS; sp++)
            s += tokp[(size_t)sp * 65536 + idx];
        tok[idx] = s;
    } else {
        int idx = (blk - 256) * 256 + tid;
        float s = 0.f;
        #pragma unroll 8
        for (int sp = 0; sp < SPLITS; sp++)
            s += normp[(size_t)sp * 1024 + idx];
        norm[idx] = s;
    }
}

// ---------------- K4: tiny attention per (b,h) + fused M ----------------
__global__ void attn_kernel(const float* __restrict__ tok,
                            const float* __restrict__ norm,
                            const float* __restrict__ Wq,
                            const float* __restrict__ Wk,
                            const float* __restrict__ Wv,
                            const float* __restrict__ Wout,
                            float* __restrict__ Mout) {
    const int bh = blockIdx.x;
    const int h = bh & 7;
    const int tx = threadIdx.x, ty = threadIdx.y;
    const int tid = ty * 16 + tx;

    __shared__ float A[64][65];
    __shared__ float Bm[64][65];
    __shared__ float Cm[64][65];

    #pragma unroll
    for (int e = 0; e < 16; e++) {
        int idx = tid + e * 256;
        int g = idx >> 6, d = idx & 63;
        A[g][d] = tok[(size_t)bh * 4096 + idx] / (norm[bh * 64 + g] + 1e-5f);
    }
    __syncthreads();

    {
        float aq[4][4] = {}, ak[4][4] = {};
        #pragma unroll
        for (int kk = 0; kk < 64; kk++) {
            float a[4];
            #pragma unroll
            for (int i = 0; i < 4; i++) a[i] = A[ty + 16 * i][kk];
            #pragma unroll
            for (int j = 0; j < 4; j++) {
                float wq = __ldg(&Wq[(tx + 16 * j) * 64 + kk]);
                float wk = __ldg(&Wk[(tx + 16 * j) * 64 + kk]);
                #pragma unroll
                for (int i = 0; i < 4; i++) {
                    aq[i][j] += a[i] * wq;
                    ak[i][j] += a[i] * wk;
                }
            }
        }
        #pragma unroll
        for (int i = 0; i < 4; i++)
            #pragma unroll
            for (int j = 0; j < 4; j++) {
                Bm[ty + 16 * i][tx + 16 * j] = aq[i][j];
                Cm[ty + 16 * i][tx + 16 * j] = ak[i][j];
            }
    }
    __syncthreads();

    {
        float L[4][4] = {};
        #pragma unroll
        for (int kk = 0; kk < 64; kk++) {
            float a[4], bv[4];
            #pragma unroll
            for (int i = 0; i < 4; i++) a[i] = Bm[ty + 16 * i][kk];
            #pragma unroll
            for (int j = 0; j < 4; j++) bv[j] = Cm[tx + 16 * j][kk];
            #pragma unroll
            for (int i = 0; i < 4; i++)
                #pragma unroll
                for (int j = 0; j < 4; j++)
                    L[i][j] += a[i] * bv[j];
        }
        #pragma unroll
        for (int i = 0; i < 4; i++) {
            #pragma unroll
            for (int j = 0; j < 4; j++) L[i][j] *= 0.125f;
            float mx = L[i][0];
            #pragma unroll
            for (int j = 1; j < 4; j++) mx = fmaxf(mx, L[i][j]);
            #pragma unroll
            for (int o = 1; o < 16; o <<= 1)
                mx = fmaxf(mx, __shfl_xor_sync(0xffffffffu, mx, o, 16));
            float s = 0.f;
            #pragma unroll
            for (int j = 0; j < 4; j++) { L[i][j] = __expf(L[i][j] - mx); s += L[i][j]; }
            #pragma unroll
            for (int o = 1; o < 16; o <<= 1)
                s += __shfl_xor_sync(0xffffffffu, s, o, 16);
            float inv = 1.0f / s;
            #pragma unroll
            for (int j = 0; j < 4; j++)
                A[ty + 16 * i][tx + 16 * j] = L[i][j] * inv;
        }
    }
    __syncthreads();

    #pragma unroll
    for (int e = 0; e < 16; e++) {
        int idx = tid + e * 256;
        int g = idx >> 6;
        Bm[g][idx & 63] = tok[(size_t)bh * 4096 + idx] / (norm[bh * 64 + g] + 1e-5f);
    }
    __syncthreads();

    {
        float av[4][4] = {};
        #pragma unroll
        for (int kk = 0; kk < 64; kk++) {
            float a[4];
            #pragma unroll
            for (int i = 0; i < 4; i++) a[i] = Bm[ty + 16 * i][kk];
            #pragma unroll
            for (int j = 0; j < 4; j++) {
                float wv = __ldg(&Wv[(tx + 16 * j) * 64 + kk]);
                #pragma unroll
                for (int i = 0; i < 4; i++) av[i][j] += a[i] * wv;
            }
        }
        __syncthreads();
        #pragma unroll
        for (int i = 0; i < 4; i++)
            #pragma unroll
            for (int j = 0; j < 4; j++)
                Cm[ty + 16 * i][tx + 16 * j] = av[i][j];
    }
    __syncthreads();

    {
        float ao[4][4] = {};
        #pragma unroll
        for (int kk = 0; kk < 64; kk++) {
            float a[4], bv[4];
            #pragma unroll
            for (int i = 0; i < 4; i++) a[i] = A[ty + 16 * i][kk];
            #pragma unroll
            for (int j = 0; j < 4; j++) bv[j] = Cm[kk][tx + 16 * j];
            #pragma unroll
            for (int i = 0; i < 4; i++)
                #pragma unroll
                for (int j = 0; j < 4; j++)
                    ao[i][j] += a[i] * bv[j];
        }
        __syncthreads();
        #pragma unroll
        for (int i = 0; i < 4; i++)
            #pragma unroll
            for (int j = 0; j < 4; j++)
                Bm[ty + 16 * i][tx + 16 * j] = ao[i][j];
    }
    __syncthreads();

    {
        float am[4][8] = {};
        #pragma unroll
        for (int kk = 0; kk < 64; kk++) {
            float a[4];
            #pragma unroll
            for (int i = 0; i < 4; i++) a[i] = Bm[ty + 16 * i][kk];
            #pragma unroll
            for (int j = 0; j < 8; j++) {
                float wv = __ldg(&Wout[(size_t)(tx + 16 * j) * INNER + h * DH + kk]);
                #pragma unroll
                for (int i = 0; i < 4; i++) am[i][j] += a[i] * wv;
            }
        }
        #pragma unroll
        for (int i = 0; i < 4; i++)
            #pragma unroll
            for (int j = 0; j < 8; j++)
                Mout[((size_t)bh * GG + ty + 16 * i) * CC + tx + 16 * j] = am[i][j];
    }
}

// ---------------- K5: fused scatter + output projection ----------------
__global__ void final_kernel(const float* __restrict__ wts,
                             const float* __restrict__ M,
                             const float* __restrict__ bout,
                             float* __restrict__ out) {
    const int b = blockIdx.y;
    const int n0 = blockIdx.x * 64;
    const int tx = threadIdx.x, ty = threadIdx.y;
    const int tid = ty * 16 + tx;

    __shared__ float As[64][17];
    __shared__ float Bs[16][128];

    float acc[4][8] = {};

    for (int h = 0; h < HEADS; h++) {
        const int bh = b * HEADS + h;
        for (int g0 = 0; g0 < GG; g0 += 16) {
            #pragma unroll
            for (int e = 0; e < 4; e++) {
                int idx = tid + e * 256;
                int m = idx >> 4, g = idx & 15;
                As[m][g] = wts[((size_t)bh * NN + n0 + m) * GG + g0 + g];
            }
            #pragma unroll
            for (int e = 0; e < 8; e++) {
                int idx = tid + e * 256;
                int k = idx >> 7, o = idx & 127;
                Bs[k][o] = M[((size_t)bh * GG + g0 + k) * CC + o];
            }
            __syncthreads();
            #pragma unroll
            for (int kk = 0; kk < 16; kk++) {
                float a[4], bv[8];
                #pragma unroll
                for (int i = 0; i < 4; i++) a[i] = As[ty + 16 * i][kk];
                #pragma unroll
                for (int j = 0; j < 8; j++) bv[j] = Bs[kk][tx + 16 * j];
                #pragma unroll
                for (int i = 0; i < 4; i++)
                    #pragma unroll
                    for (int j = 0; j < 8; j++)
                        acc[i][j] += a[i] * bv[j];
            }
            __syncthreads();
        }
    }

    #pragma unroll
    for (int i = 0; i < 4; i++) {
        int n = n0 + ty + 16 * i;
        #pragma unroll
        for (int j = 0; j < 8; j++) {
            int o = tx + 16 * j;
            out[((size_t)b * NN + n) * CC + o] = acc[i][j] + bout[o];
        }
    }
}

// ---------------- launch ----------------
extern "C" void kernel_launch(void* const* d_in, const int* in_sizes, int n_in,
                              void* d_out, int out_size) {
    const float* x     = (const float*)d_in[0];
    const float* Wfx   = (const float*)d_in[1];
    const float* bfx   = (const float*)d_in[2];
    const float* Wx    = (const float*)d_in[3];
    const float* bx    = (const float*)d_in[4];
    const float* Wsl   = (const float*)d_in[5];
    const float* bsl   = (const float*)d_in[6];
    const float* temp  = (const float*)d_in[7];
    const float* Wq    = (const float*)d_in[8];
    const float* Wk    = (const float*)d_in[9];
    const float* Wv    = (const float*)d_in[10];
    const float* Wout  = (const float*)d_in[11];
    const float* bout  = (const float*)d_in[12];
    float* out = (float*)d_out;

    float *p_fx, *p_xm, *p_w, *p_tokp, *p_normp, *p_tok, *p_norm, *p_M;
    __nv_bfloat16 *p_xhi, *p_xlo, *p_whi, *p_wlo;
    cudaGetSymbolAddress((void**)&p_fx, g_fx);
    cudaGetSymbolAddress((void**)&p_xm, g_xm);
    cudaGetSymbolAddress((void**)&p_w, g_w);
    cudaGetSymbolAddress((void**)&p_tokp, g_tokp);
    cudaGetSymbolAddress((void**)&p_normp, g_normp);
    cudaGetSymbolAddress((void**)&p_tok, g_tok);
    cudaGetSymbolAddress((void**)&p_norm, g_norm);
    cudaGetSymbolAddress((void**)&p_M, g_M);
    cudaGetSymbolAddress((void**)&p_xhi, g_xhi);
    cudaGetSymbolAddress((void**)&p_xlo, g_xlo);
    cudaGetSymbolAddress((void**)&p_whi, g_whi);
    cudaGetSymbolAddress((void**)&p_wlo, g_wlo);

    static bool attr_set = false;
    if (!attr_set) {
        cudaFuncSetAttribute(conv_mma_kernel,
                             cudaFuncAttributeMaxDynamicSharedMemorySize, 65536);
        attr_set = true;
    }

    dim3 blk(16, 16);

    // 0. bf16 3-split staging
    split_x_kernel<<<(BB * NN * CC) / 256, 256>>>(x, p_xhi, p_xlo);
    split_w_kernel<<<(1024 * KTOT) / 256, 256>>>(Wfx, Wx, p_whi, p_wlo);

    // 1. fused dual conv on tensor cores
    conv_mma_kernel<<<dim3(8, 512, BB), 256, 65536>>>(
        p_xhi, p_xlo, p_whi, p_wlo, bfx, bx, p_fx, p_xm);

    // 2. logits + softmax -> slice weights
    logits_softmax_kernel<<<dim3(NN / 64, BB * HEADS), blk>>>(p_xm, Wsl, bsl, temp, p_w);

    // 3. slice token split-K partials + reduce
    token_reduce_kernel<<<dim3(SPLITS, BB * HEADS), blk>>>(p_w, p_fx, p_tokp, p_normp);
    split_reduce_kernel<<<260, 256>>>(p_tokp, p_normp, p_tok, p_norm);

    // 4. tiny attention + fused Wout fold
    attn_kernel<<<BB * HEADS, blk>>>(p_tok, p_norm, Wq, Wk, Wv, Wout, p_M);

    // 5. fused scatter + projection
    final_kernel<<<dim3(NN / 64, BB), blk>>>(p_w, p_M, bout, out);
}

// round 3
// speedup vs baseline: 2.4631x; 1.0697x over previous
#include <cuda_runtime.h>
#include <cuda_bf16.h>
#include <math.h>
#include <stdint.h>

// Problem constants
#define BB 2
#define HH 256
#define WW 256
#define NN 65536          // H*W
#define CC 128
#define HEADS 8
#define DH 64             // dim_head
#define GG 64             // SLICE
#define INNER 512         // HEADS*DH
#define SPLITS 64         // split-K for token reduction
#define CHUNK 1024        // tokens per split (NN/SPLITS)
#define KTOT 1152         // 9 taps * 128 channels

// ---------------- device scratch (static, no allocs) ----------------
__device__ float g_fx[(size_t)BB * NN * INNER];      // fx_mid  [b][n][inner]
__device__ float g_xm[(size_t)BB * NN * INNER];      // x_mid   [b][n][inner]
__device__ float g_tokp[(size_t)SPLITS * BB * HEADS * GG * DH];
__device__ float g_normp[(size_t)SPLITS * BB * HEADS * GG];
__device__ float g_tok [(size_t)BB * HEADS * GG * DH];
__device__ float g_norm[(size_t)BB * HEADS * GG];

// slice weights as bf16 hi/lo pair  [bh][n][g]
__device__ __align__(16) __nv_bfloat16 g_swhi[(size_t)BB * HEADS * NN * GG];
__device__ __align__(16) __nv_bfloat16 g_swlo[(size_t)BB * HEADS * NN * GG];
// Mt = (out_slice · Wout^T) transposed: [b][o][h*64+g], bf16 hi/lo
__device__ __align__(16) __nv_bfloat16 g_Mthi[(size_t)BB * CC * INNER];
__device__ __align__(16) __nv_bfloat16 g_Mtlo[(size_t)BB * CC * INNER];

// bf16 3-split staging for conv
__device__ __align__(16) __nv_bfloat16 g_xhi[(size_t)BB * NN * CC];
__device__ __align__(16) __nv_bfloat16 g_xlo[(size_t)BB * NN * CC];
__device__ __align__(16) __nv_bfloat16 g_whi[(size_t)1024 * KTOT];  // [oc'][k]
__device__ __align__(16) __nv_bfloat16 g_wlo[(size_t)1024 * KTOT];

// ---------------- prep: split fp32 -> bf16 hi + bf16 lo ----------------
__global__ void split_x_kernel(const float* __restrict__ x,
                               __nv_bfloat16* __restrict__ xhi,
                               __nv_bfloat16* __restrict__ xlo) {
    size_t i = (size_t)blockIdx.x * 256 + threadIdx.x;
    float f = x[i];
    __nv_bfloat16 h = __float2bfloat16(f);
    float r = f - __bfloat162float(h);
    xhi[i] = h;
    xlo[i] = __float2bfloat16(r);
}

__global__ void split_w_kernel(const float* __restrict__ Wfx,
                               const float* __restrict__ Wx,
                               __nv_bfloat16* __restrict__ whi,
                               __nv_bfloat16* __restrict__ wlo) {
    int i = blockIdx.x * 256 + threadIdx.x;
    int oc = i / KTOT;
    int k  = i - oc * KTOT;
    float f = (oc < 512) ? Wfx[(size_t)k * 512 + oc]
                         : Wx [(size_t)k * 512 + oc - 512];
    __nv_bfloat16 h = __float2bfloat16(f);
    float r = f - __bfloat162float(h);
    whi[i] = h;
    wlo[i] = __float2bfloat16(r);
}

// ---------------- shared MMA plumbing ----------------
__device__ __forceinline__ void cp16(uint32_t saddr, const void* g, bool valid) {
    int sz = valid ? 16 : 0;
    asm volatile("cp.async.cg.shared.global [%0], [%1], 16, %2;\n"
                 :: "r"(saddr), "l"(g), "r"(sz));
}

__device__ __forceinline__ uint32_t lds_frag(const uint32_t* base, int row, int kw) {
    return base[row * 16 + ((((kw >> 2) ^ (row & 3)) << 2) | (kw & 3))];
}

__device__ __forceinline__ void mma_bf16(float c[4], uint32_t a0, uint32_t a1,
                                         uint32_t a2, uint32_t a3,
                                         uint32_t b0, uint32_t b1) {
    asm volatile(
        "mma.sync.aligned.m16n8k16.row.col.f32.bf16.bf16.f32 "
        "{%0,%1,%2,%3}, {%4,%5,%6,%7}, {%8,%9}, {%0,%1,%2,%3};"
        : "+f"(c[0]), "+f"(c[1]), "+f"(c[2]), "+f"(c[3])
        : "r"(a0), "r"(a1), "r"(a2), "r"(a3), "r"(b0), "r"(b1));
}

// ---------------- conv as implicit GEMM on tensor cores ----------------
__device__ __forceinline__ void load_tile(
    uint32_t sbase_bytes,
    const __nv_bfloat16* __restrict__ Xhi, const __nv_bfloat16* __restrict__ Xlo,
    const __nv_bfloat16* __restrict__ Whi, const __nv_bfloat16* __restrict__ Wlo,
    int it, int b, int hrow, int w0, int ocb, int tid)
{
    const int kg  = it * 32;
    const int tap = kg >> 7;
    const int dy = tap / 3 - 1, dx = tap % 3 - 1;
    const int c0 = kg & 127;
    const int hp = hrow + dy;
    const bool hok = (hp >= 0) && (hp < HH);

    #pragma unroll
    for (int j = 0; j < 8; j++) {
        int id  = tid + j * 256;
        int arr = id >> 9;              // 0:Ahi 1:Alo 2:Bhi 3:Blo
        int c   = id & 511;
        int row = c >> 2;
        int c4  = c & 3;
        uint32_t woff = (uint32_t)row * 16 + ((c4 ^ (row & 3)) << 2);
        uint32_t saddr = sbase_bytes + (arr * 2048 + woff) * 4;
        const __nv_bfloat16* g;
        bool valid;
        if (arr < 2) {
            int wp = w0 + row + dx;
            valid = hok && (wp >= 0) && (wp < WW);
            int wpc = valid ? wp : 0;
            int hpc = (hok) ? hp : 0;
            size_t off = (((size_t)b * NN + (size_t)hpc * WW + wpc) * CC + c0 + c4 * 8);
            g = (arr == 0 ? Xhi : Xlo) + off;
        } else {
            int ocr = ocb * 128 + row;
            size_t off = (size_t)ocr * KTOT + kg + c4 * 8;
            g = (arr == 2 ? Whi : Wlo) + off;
            valid = true;
        }
        cp16(saddr, g, valid);
    }
}

__global__ __launch_bounds__(256, 1)
void conv_mma_kernel(const __nv_bfloat16* __restrict__ Xhi,
                     const __nv_bfloat16* __restrict__ Xlo,
                     const __nv_bfloat16* __restrict__ Whi,
                     const __nv_bfloat16* __restrict__ Wlo,
                     const float* __restrict__ bfx,
                     const float* __restrict__ bx,
                     float* __restrict__ ofx,
                     float* __restrict__ oxm)
{
    extern __shared__ uint32_t smem_u32[];   // 3 stages * 4 arrays * 2048 words

    const int ocb = blockIdx.x;
    const int pt  = blockIdx.y;
    const int b   = blockIdx.z;
    const int n0  = pt * 128;
    const int hrow = n0 >> 8;
    const int w0   = n0 & 255;

    const int tid  = threadIdx.x;
    const int wid  = tid >> 5;
    const int lane = tid & 31;
    const int grp  = lane >> 2;
    const int tid4 = lane & 3;
    const int wm   = wid & 1;
    const int wn   = wid >> 1;

    float acc[4][4][4];
    #pragma unroll
    for (int i = 0; i < 4; i++)
        #pragma unroll
        for (int j = 0; j < 4; j++)
            #pragma unroll
            for (int r = 0; r < 4; r++) acc[i][j][r] = 0.f;

    uint32_t sbase = (uint32_t)__cvta_generic_to_shared(smem_u32);

    load_tile(sbase, Xhi, Xlo, Whi, Wlo, 0, b, hrow, w0, ocb, tid);
    asm volatile("cp.async.commit_group;\n" ::: "memory");
    load_tile(sbase + 32768, Xhi, Xlo, Whi, Wlo, 1, b, hrow, w0, ocb, tid);
    asm volatile("cp.async.commit_group;\n" ::: "memory");

    for (int it = 0; it < 36; ++it) {
        const int cur = it % 3;
        if (it + 2 < 36)
            load_tile(sbase + (uint32_t)((it + 2) % 3) * 32768,
                      Xhi, Xlo, Whi, Wlo, it + 2, b, hrow, w0, ocb, tid);
        asm volatile("cp.async.commit_group;\n" ::: "memory");
        asm volatile("cp.async.wait_group 2;\n" ::: "memory");
        __syncthreads();

        const uint32_t* Ahi = smem_u32 + (size_t)cur * 8192;
        const uint32_t* Alo = Ahi + 2048;
        const uint32_t* Bhi = Ahi + 4096;
        const uint32_t* Blo = Ahi + 6144;

        #pragma unroll
        for (int s = 0; s < 2; s++) {
            const int kwb = s * 8;
            uint32_t ah[4][4], al[4][4];
            #pragma unroll
            for (int mi = 0; mi < 4; mi++) {
                int r0 = wm * 64 + mi * 16 + grp;
                ah[mi][0] = lds_frag(Ahi, r0,     kwb + tid4);
                ah[mi][1] = lds_frag(Ahi, r0 + 8, kwb + tid4);
                ah[mi][2] = lds_frag(Ahi, r0,     kwb + tid4 + 4);
                ah[mi][3] = lds_frag(Ahi, r0 + 8, kwb + tid4 + 4);
                al[mi][0] = lds_frag(Alo, r0,     kwb + tid4);
                al[mi][1] = lds_frag(Alo, r0 + 8, kwb + tid4);
                al[mi][2] = lds_frag(Alo, r0,     kwb + tid4 + 4);
                al[mi][3] = lds_frag(Alo, r0 + 8, kwb + tid4 + 4);
            }
            uint32_t bh[4][2], bl[4][2];
            #pragma unroll
            for (int ni = 0; ni < 4; ni++) {
                int r0 = wn * 32 + ni * 8 + grp;
                bh[ni][0] = lds_frag(Bhi, r0, kwb + tid4);
                bh[ni][1] = lds_frag(Bhi, r0, kwb + tid4 + 4);
                bl[ni][0] = lds_frag(Blo, r0, kwb + tid4);
                bl[ni][1] = lds_frag(Blo, r0, kwb + tid4 + 4);
            }
            #pragma unroll
            for (int mi = 0; mi < 4; mi++)
                #pragma unroll
                for (int ni = 0; ni < 4; ni++) {
                    mma_bf16(acc[mi][ni], ah[mi][0], ah[mi][1], ah[mi][2], ah[mi][3],
                             bh[ni][0], bh[ni][1]);
                    mma_bf16(acc[mi][ni], ah[mi][0], ah[mi][1], ah[mi][2], ah[mi][3],
                             bl[ni][0], bl[ni][1]);
                    mma_bf16(acc[mi][ni], al[mi][0], al[mi][1], al[mi][2], al[mi][3],
                             bh[ni][0], bh[ni][1]);
                }
        }
        __syncthreads();
    }

    const bool is_fx = (ocb < 4);
    float* outp = is_fx ? ofx : oxm;
    const float* biasp = is_fx ? bfx : bx;
    const int ocbase = (ocb & 3) * 128;

    #pragma unroll
    for (int mi = 0; mi < 4; mi++) {
        int row = wm * 64 + mi * 16 + grp;
        int n  = n0 + row;
        #pragma unroll
        for (int ni = 0; ni < 4; ni++) {
            int col = wn * 32 + ni * 8 + tid4 * 2;
            int oc  = ocbase + col;
            float b0v = biasp[oc], b1v = biasp[oc + 1];
            size_t base0 = ((size_t)b * NN + n) * INNER + oc;
            outp[base0]     = acc[mi][ni][0] + b0v;
            outp[base0 + 1] = acc[mi][ni][1] + b1v;
            size_t base1 = ((size_t)b * NN + n + 8) * INNER + oc;
            outp[base1]     = acc[mi][ni][2] + b0v;
            outp[base1 + 1] = acc[mi][ni][3] + b1v;
        }
    }
}

// ---------------- K2: slice logits + softmax -> bf16 hi/lo weights ----------------
__global__ void logits_softmax_kernel(const float* __restrict__ xm,
                                      const float* __restrict__ Wslice,
                                      const float* __restrict__ bslice,
                                      const float* __restrict__ temperature,
                                      __nv_bfloat16* __restrict__ whi,
                                      __nv_bfloat16* __restrict__ wlo) {
    const int bh = blockIdx.y;
    const int b = bh >> 3, h = bh & 7;
    const int n0 = blockIdx.x * 64;
    const int tx = threadIdx.x, ty = threadIdx.y;
    const int tid = ty * 16 + tx;

    __shared__ float Xs[64][65];
    __shared__ float Ws[64][65];

    #pragma unroll
    for (int e = 0; e < 16; e++) {
        int idx = tid + e * 256;
        int m = idx >> 6, d = idx & 63;
        Xs[m][d] = xm[((size_t)b * NN + n0 + m) * INNER + h * DH + d];
        Ws[m][d] = Wslice[idx];
    }
    __syncthreads();

    float acc[4][4] = {};
    #pragma unroll
    for (int kk = 0; kk < 64; kk++) {
        float a[4], bv[4];
        #pragma unroll
        for (int i = 0; i < 4; i++) a[i] = Xs[ty + 16 * i][kk];
        #pragma unroll
        for (int j = 0; j < 4; j++) bv[j] = Ws[tx + 16 * j][kk];
        #pragma unroll
        for (int i = 0; i < 4; i++)
            #pragma unroll
            for (int j = 0; j < 4; j++)
                acc[i][j] += a[i] * bv[j];
    }

    float temp = temperature[h];
    temp = fminf(fmaxf(temp, 0.1f), 5.0f);
    const float inv_t = 1.0f / temp;

    #pragma unroll
    for (int j = 0; j < 4; j++) {
        float bs = bslice[tx + 16 * j];
        #pragma unroll
        for (int i = 0; i < 4; i++)
            acc[i][j] = (acc[i][j] + bs) * inv_t;
    }

    #pragma unroll
    for (int i = 0; i < 4; i++) {
        float mx = acc[i][0];
        #pragma unroll
        for (int j = 1; j < 4; j++) mx = fmaxf(mx, acc[i][j]);
        #pragma unroll
        for (int o = 1; o < 16; o <<= 1)
            mx = fmaxf(mx, __shfl_xor_sync(0xffffffffu, mx, o, 16));
        float s = 0.f;
        #pragma unroll
        for (int j = 0; j < 4; j++) { acc[i][j] = __expf(acc[i][j] - mx); s += acc[i][j]; }
        #pragma unroll
        for (int o = 1; o < 16; o <<= 1)
            s += __shfl_xor_sync(0xffffffffu, s, o, 16);
        float inv = 1.0f / s;
        int n = n0 + ty + 16 * i;
        #pragma unroll
        for (int j = 0; j < 4; j++) {
            float v = acc[i][j] * inv;
            __nv_bfloat16 hv = __float2bfloat16(v);
            float r = v - __bfloat162float(hv);
            size_t idx = ((size_t)bh * NN + n) * GG + tx + 16 * j;
            whi[idx] = hv;
            wlo[idx] = __float2bfloat16(r);
        }
    }
}

// ---------------- K3: split-K reduction: slice_token partials ----------------
__global__ void token_reduce_kernel(const __nv_bfloat16* __restrict__ whi,
                                    const __nv_bfloat16* __restrict__ wlo,
                                    const float* __restrict__ fx,
                                    float* __restrict__ tokp,
                                    float* __restrict__ normp) {
    const int bh = blockIdx.y;
    const int b = bh >> 3, h = bh & 7;
    const int split = blockIdx.x;
    const int nbase = split * CHUNK;
    const int tx = threadIdx.x, ty = threadIdx.y;
    const int tid = ty * 16 + tx;

    __shared__ float wb[8][64];
    __shared__ float fb[8][64];

    float acc[4][4] = {};
    float nacc[4] = {};

    for (int t0 = 0; t0 < CHUNK; t0 += 8) {
        #pragma unroll
        for (int e = 0; e < 2; e++) {
            int idx = tid + e * 256;
            int t = idx >> 6, q = idx & 63;
            int n = nbase + t0 + t;
            size_t wi = ((size_t)bh * NN + n) * GG + q;
            wb[t][q] = __bfloat162float(whi[wi]) + __bfloat162float(wlo[wi]);
            fb[t][q] = fx[((size_t)b * NN + n) * INNER + h * DH + q];
        }
        __syncthreads();
        #pragma unroll
        for (int t = 0; t < 8; t++) {
            float a[4], bv[4];
            #pragma unroll
            for (int i = 0; i < 4; i++) a[i] = wb[t][ty + 16 * i];
            #pragma unroll
            for (int j = 0; j < 4; j++) bv[j] = fb[t][tx + 16 * j];
            #pragma unroll
            for (int i = 0; i < 4; i++)
                #pragma unroll
                for (int j = 0; j < 4; j++)
                    acc[i][j] += a[i] * bv[j];
            if (tx == 0) {
                #pragma unroll
                for (int i = 0; i < 4; i++) nacc[i] += a[i];
            }
        }
        __syncthreads();
    }

    const size_t base = ((size_t)split * (BB * HEADS) + bh) * (GG * DH);
    #pragma unroll
    for (int i = 0; i < 4; i++)
        #pragma unroll
        for (int j = 0; j < 4; j++)
            tokp[base + (size_t)(ty + 16 * i) * DH + tx + 16 * j] = acc[i][j];
    if (tx == 0) {
        #pragma unroll
        for (int i = 0; i < 4; i++)
            normp[((size_t)split * (BB * HEADS) + bh) * GG + ty + 16 * i] = nacc[i];
    }
}

// ---------------- K3b: deterministic split reduction ----------------
__global__ void split_reduce_kernel(const float* __restrict__ tokp,
                                    const float* __restrict__ normp,
                                    float* __restrict__ tok,
                                    float* __restrict__ norm) {
    const int blk = blockIdx.x;
    const int tid = threadIdx.x;
    if (blk < 256) {
        int idx = blk * 256 + tid;
        float s = 0.f;
        #pragma unroll 8
        for (int sp = 0; sp < SPLITS; sp++)
            s += tokp[(size_t)sp * 65536 + idx];
        tok[idx] = s;
    } else {
        int idx = (blk - 256) * 256 + tid;
        float s = 0.f;
        #pragma unroll 8
        for (int sp = 0; sp < SPLITS; sp++)
            s += normp[(size_t)sp * 1024 + idx];
        norm[idx] = s;
    }
}

// ---------------- K4: tiny attention per (b,h), emits Mt bf16 hi/lo ----------------
__global__ void attn_kernel(const float* __restrict__ tok,
                            const float* __restrict__ norm,
                            const float* __restrict__ Wq,
                            const float* __restrict__ Wk,
                            const float* __restrict__ Wv,
                            const float* __restrict__ Wout,
                            __nv_bfloat16* __restrict__ Mthi,
                            __nv_bfloat16* __restrict__ Mtlo) {
    const int bh = blockIdx.x;
    const int b = bh >> 3, h = bh & 7;
    const int tx = threadIdx.x, ty = threadIdx.y;
    const int tid = ty * 16 + tx;

    __shared__ float A[64][65];
    __shared__ float Bm[64][65];
    __shared__ float Cm[64][65];

    #pragma unroll
    for (int e = 0; e < 16; e++) {
        int idx = tid + e * 256;
        int g = idx >> 6, d = idx & 63;
        A[g][d] = tok[(size_t)bh * 4096 + idx] / (norm[bh * 64 + g] + 1e-5f);
    }
    __syncthreads();

    {
        float aq[4][4] = {}, ak[4][4] = {};
        #pragma unroll
        for (int kk = 0; kk < 64; kk++) {
            float a[4];
            #pragma unroll
            for (int i = 0; i < 4; i++) a[i] = A[ty + 16 * i][kk];
            #pragma unroll
            for (int j = 0; j < 4; j++) {
                float wq = __ldg(&Wq[(tx + 16 * j) * 64 + kk]);
                float wk = __ldg(&Wk[(tx + 16 * j) * 64 + kk]);
                #pragma unroll
                for (int i = 0; i < 4; i++) {
                    aq[i][j] += a[i] * wq;
                    ak[i][j] += a[i] * wk;
                }
            }
        }
        #pragma unroll
        for (int i = 0; i < 4; i++)
            #pragma unroll
            for (int j = 0; j < 4; j++) {
                Bm[ty + 16 * i][tx + 16 * j] = aq[i][j];
                Cm[ty + 16 * i][tx + 16 * j] = ak[i][j];
            }
    }
    __syncthreads();

    {
        float L[4][4] = {};
        #pragma unroll
        for (int kk = 0; kk < 64; kk++) {
            float a[4], bv[4];
            #pragma unroll
            for (int i = 0; i < 4; i++) a[i] = Bm[ty + 16 * i][kk];
            #pragma unroll
            for (int j = 0; j < 4; j++) bv[j] = Cm[tx + 16 * j][kk];
            #pragma unroll
            for (int i = 0; i < 4; i++)
                #pragma unroll
                for (int j = 0; j < 4; j++)
                    L[i][j] += a[i] * bv[j];
        }
        #pragma unroll
        for (int i = 0; i < 4; i++) {
            #pragma unroll
            for (int j = 0; j < 4; j++) L[i][j] *= 0.125f;
            float mx = L[i][0];
            #pragma unroll
            for (int j = 1; j < 4; j++) mx = fmaxf(mx, L[i][j]);
            #pragma unroll
            for (int o = 1; o < 16; o <<= 1)
                mx = fmaxf(mx, __shfl_xor_sync(0xffffffffu, mx, o, 16));
            float s = 0.f;
            #pragma unroll
            for (int j = 0; j < 4; j++) { L[i][j] = __expf(L[i][j] - mx); s += L[i][j]; }
            #pragma unroll
            for (int o = 1; o < 16; o <<= 1)
                s += __shfl_xor_sync(0xffffffffu, s, o, 16);
            float inv = 1.0f / s;
            #pragma unroll
            for (int j = 0; j < 4; j++)
                A[ty + 16 * i][tx + 16 * j] = L[i][j] * inv;
        }
    }
    __syncthreads();

    #pragma unroll
    for (int e = 0; e < 16; e++) {
        int idx = tid + e * 256;
        int g = idx >> 6;
        Bm[g][idx & 63] = tok[(size_t)bh * 4096 + idx] / (norm[bh * 64 + g] + 1e-5f);
    }
    __syncthreads();

    {
        float av[4][4] = {};
        #pragma unroll
        for (int kk = 0; kk < 64; kk++) {
            float a[4];
            #pragma unroll
            for (int i = 0; i < 4; i++) a[i] = Bm[ty + 16 * i][kk];
            #pragma unroll
            for (int j = 0; j < 4; j++) {
                float wv = __ldg(&Wv[(tx + 16 * j) * 64 + kk]);
                #pragma unroll
                for (int i = 0; i < 4; i++) av[i][j] += a[i] * wv;
            }
        }
        __syncthreads();
        #pragma unroll
        for (int i = 0; i < 4; i++)
            #pragma unroll
            for (int j = 0; j < 4; j++)
                Cm[ty + 16 * i][tx + 16 * j] = av[i][j];
    }
    __syncthreads();

    {
        float ao[4][4] = {};
        #pragma unroll
        for (int kk = 0; kk < 64; kk++) {
            float a[4], bv[4];
            #pragma unroll
            for (int i = 0; i < 4; i++) a[i] = A[ty + 16 * i][kk];
            #pragma unroll
            for (int j = 0; j < 4; j++) bv[j] = Cm[kk][tx + 16 * j];
            #pragma unroll
            for (int i = 0; i < 4; i++)
                #pragma unroll
                for (int j = 0; j < 4; j++)
                    ao[i][j] += a[i] * bv[j];
        }
        __syncthreads();
        #pragma unroll
        for (int i = 0; i < 4; i++)
            #pragma unroll
            for (int j = 0; j < 4; j++)
                Bm[ty + 16 * i][tx + 16 * j] = ao[i][j];
    }
    __syncthreads();

    // M^T[o][h*64+g] = sum_d out_slice[g][d]*Wout[o][h*64+d], as bf16 hi/lo
    {
        float am[4][8] = {};
        #pragma unroll
        for (int kk = 0; kk < 64; kk++) {
            float a[4];
            #pragma unroll
            for (int i = 0; i < 4; i++) a[i] = Bm[ty + 16 * i][kk];
            #pragma unroll
            for (int j = 0; j < 8; j++) {
                float wv = __ldg(&Wout[(size_t)(tx + 16 * j) * INNER + h * DH + kk]);
                #pragma unroll
                for (int i = 0; i < 4; i++) am[i][j] += a[i] * wv;
            }
        }
        #pragma unroll
        for (int i = 0; i < 4; i++) {
            int g = ty + 16 * i;
            #pragma unroll
            for (int j = 0; j < 8; j++) {
                int o = tx + 16 * j;
                float v = am[i][j];
                __nv_bfloat16 hv = __float2bfloat16(v);
                float r = v - __bfloat162float(hv);
                size_t idx = ((size_t)b * CC + o) * INNER + h * DH + g;
                Mthi[idx] = hv;
                Mtlo[idx] = __float2bfloat16(r);
            }
        }
    }
}

// ---------------- K5: fused scatter + projection on tensor cores ----------------
// out[n][o] = bout[o] + sum_{h,g} w[bh][n][g] * Mt[b][o][h*64+g]
__global__ __launch_bounds__(256)
void final_mma_kernel(const __nv_bfloat16* __restrict__ Whi,
                      const __nv_bfloat16* __restrict__ Wlo,
                      const __nv_bfloat16* __restrict__ Mthi,
                      const __nv_bfloat16* __restrict__ Mtlo,
                      const float* __restrict__ bout,
                      float* __restrict__ out)
{
    extern __shared__ uint32_t smem_u32[];   // 2 stages * 4 arrays * 2048 words

    const int pt = blockIdx.x;               // 0..1023
    const int b  = pt >> 9;
    const int n0 = (pt & 511) * 128;

    const int tid  = threadIdx.x;
    const int wid  = tid >> 5;
    const int lane = tid & 31;
    const int grp  = lane >> 2;
    const int tid4 = lane & 3;
    const int wm   = wid & 1;
    const int wn   = wid >> 1;

    float acc[4][4][4];
    #pragma unroll
    for (int i = 0; i < 4; i++)
        #pragma unroll
        for (int j = 0; j < 4; j++)
            #pragma unroll
            for (int r = 0; r < 4; r++) acc[i][j][r] = 0.f;

    uint32_t sbase = (uint32_t)__cvta_generic_to_shared(smem_u32);

    // loader: it in [0,16): h = it>>1, g0 = (it&1)*32
    auto load_fin = [&](uint32_t sb, int it) {
        const int h  = it >> 1;
        const int g0 = (it & 1) * 32;
        #pragma unroll
        for (int j = 0; j < 8; j++) {
            int id  = tid + j * 256;
            int arr = id >> 9;
            int c   = id & 511;
            int row = c >> 2;
            int c4  = c & 3;
            uint32_t woff = (uint32_t)row * 16 + ((c4 ^ (row & 3)) << 2);
            uint32_t saddr = sb + (arr * 2048 + woff) * 4;
            const __nv_bfloat16* g;
            if (arr < 2) {
                size_t off = (((size_t)(b * HEADS + h) * NN) + n0 + row) * GG + g0 + c4 * 8;
                g = (arr == 0 ? Whi : Wlo) + off;
            } else {
                size_t off = ((size_t)b * CC + row) * INNER + h * DH + g0 + c4 * 8;
                g = (arr == 2 ? Mthi : Mtlo) + off;
            }
            cp16(saddr, g, true);
        }
    };

    load_fin(sbase, 0);
    asm volatile("cp.async.commit_group;\n" ::: "memory");

    for (int it = 0; it < 16; ++it) {
        const int cur = it & 1;
        if (it + 1 < 16) {
            load_fin(sbase + (uint32_t)(1 - cur) * 32768, it + 1);
            asm volatile("cp.async.commit_group;\n" ::: "memory");
            asm volatile("cp.async.wait_group 1;\n" ::: "memory");
        } else {
            asm volatile("cp.async.wait_group 0;\n" ::: "memory");
        }
        __syncthreads();

        const uint32_t* Ahi = smem_u32 + (size_t)cur * 8192;
        const uint32_t* Alo = Ahi + 2048;
        const uint32_t* Bhi = Ahi + 4096;
        const uint32_t* Blo = Ahi + 6144;

        #pragma unroll
        for (int s = 0; s < 2; s++) {
            const int kwb = s * 8;
            uint32_t ah[4][4], al[4][4];
            #pragma unroll
            for (int mi = 0; mi < 4; mi++) {
                int r0 = wm * 64 + mi * 16 + grp;
                ah[mi][0] = lds_frag(Ahi, r0,     kwb + tid4);
                ah[mi][1] = lds_frag(Ahi, r0 + 8, kwb + tid4);
                ah[mi][2] = lds_frag(Ahi, r0,     kwb + tid4 + 4);
                ah[mi][3] = lds_frag(Ahi, r0 + 8, kwb + tid4 + 4);
                al[mi][0] = lds_frag(Alo, r0,     kwb + tid4);
                al[mi][1] = lds_frag(Alo, r0 + 8, kwb + tid4);
                al[mi][2] = lds_frag(Alo, r0,     kwb + tid4 + 4);
                al[mi][3] = lds_frag(Alo, r0 + 8, kwb + tid4 + 4);
            }
            uint32_t bh[4][2], bl[4][2];
            #pragma unroll
            for (int ni = 0; ni < 4; ni++) {
                int r0 = wn * 32 + ni * 8 + grp;
                bh[ni][0] = lds_frag(Bhi, r0, kwb + tid4);
                bh[ni][1] = lds_frag(Bhi, r0, kwb + tid4 + 4);
                bl[ni][0] = lds_frag(Blo, r0, kwb + tid4);
                bl[ni][1] = lds_frag(Blo, r0, kwb + tid4 + 4);
            }
            #pragma unroll
            for (int mi = 0; mi < 4; mi++)
                #pragma unroll
                for (int ni = 0; ni < 4; ni++) {
                    mma_bf16(acc[mi][ni], ah[mi][0], ah[mi][1], ah[mi][2], ah[mi][3],
                             bh[ni][0], bh[ni][1]);
                    mma_bf16(acc[mi][ni], ah[mi][0], ah[mi][1], ah[mi][2], ah[mi][3],
                             bl[ni][0], bl[ni][1]);
                    mma_bf16(acc[mi][ni], al[mi][0], al[mi][1], al[mi][2], al[mi][3],
                             bh[ni][0], bh[ni][1]);
                }
        }
        __syncthreads();
    }

    #pragma unroll
    for (int mi = 0; mi < 4; mi++) {
        int row = wm * 64 + mi * 16 + grp;
        int n  = n0 + row;
        #pragma unroll
        for (int ni = 0; ni < 4; ni++) {
            int oc = wn * 32 + ni * 8 + tid4 * 2;
            float b0v = bout[oc], b1v = bout[oc + 1];
            size_t base0 = ((size_t)b * NN + n) * CC + oc;
            out[base0]     = acc[mi][ni][0] + b0v;
            out[base0 + 1] = acc[mi][ni][1] + b1v;
            size_t base1 = ((size_t)b * NN + n + 8) * CC + oc;
            out[base1]     = acc[mi][ni][2] + b0v;
            out[base1 + 1] = acc[mi][ni][3] + b1v;
        }
    }
}

// ---------------- launch ----------------
extern "C" void kernel_launch(void* const* d_in, const int* in_sizes, int n_in,
                              void* d_out, int out_size) {
    const float* x     = (const float*)d_in[0];
    const float* Wfx   = (const float*)d_in[1];
    const float* bfx   = (const float*)d_in[2];
    const float* Wx    = (const float*)d_in[3];
    const float* bx    = (const float*)d_in[4];
    const float* Wsl   = (const float*)d_in[5];
    const float* bsl   = (const float*)d_in[6];
    const float* temp  = (const float*)d_in[7];
    const float* Wq    = (const float*)d_in[8];
    const float* Wk    = (const float*)d_in[9];
    const float* Wv    = (const float*)d_in[10];
    const float* Wout  = (const float*)d_in[11];
    const float* bout  = (const float*)d_in[12];
    float* out = (float*)d_out;

    float *p_fx, *p_xm, *p_tokp, *p_normp, *p_tok, *p_norm;
    __nv_bfloat16 *p_xhi, *p_xlo, *p_whi, *p_wlo;
    __nv_bfloat16 *p_swhi, *p_swlo, *p_Mthi, *p_Mtlo;
    cudaGetSymbolAddress((void**)&p_fx, g_fx);
    cudaGetSymbolAddress((void**)&p_xm, g_xm);
    cudaGetSymbolAddress((void**)&p_tokp, g_tokp);
    cudaGetSymbolAddress((void**)&p_normp, g_normp);
    cudaGetSymbolAddress((void**)&p_tok, g_tok);
    cudaGetSymbolAddress((void**)&p_norm, g_norm);
    cudaGetSymbolAddress((void**)&p_xhi, g_xhi);
    cudaGetSymbolAddress((void**)&p_xlo, g_xlo);
    cudaGetSymbolAddress((void**)&p_whi, g_whi);
    cudaGetSymbolAddress((void**)&p_wlo, g_wlo);
    cudaGetSymbolAddress((void**)&p_swhi, g_swhi);
    cudaGetSymbolAddress((void**)&p_swlo, g_swlo);
    cudaGetSymbolAddress((void**)&p_Mthi, g_Mthi);
    cudaGetSymbolAddress((void**)&p_Mtlo, g_Mtlo);

    static bool attr_set = false;
    if (!attr_set) {
        cudaFuncSetAttribute(conv_mma_kernel,
                             cudaFuncAttributeMaxDynamicSharedMemorySize, 98304);
        cudaFuncSetAttribute(final_mma_kernel,
                             cudaFuncAttributeMaxDynamicSharedMemorySize, 65536);
        attr_set = true;
    }

    dim3 blk(16, 16);

    // 0. bf16 3-split staging
    split_x_kernel<<<(BB * NN * CC) / 256, 256>>>(x, p_xhi, p_xlo);
    split_w_kernel<<<(1024 * KTOT) / 256, 256>>>(Wfx, Wx, p_whi, p_wlo);

    // 1. fused dual conv on tensor cores (3-stage pipeline)
    conv_mma_kernel<<<dim3(8, 512, BB), 256, 98304>>>(
        p_xhi, p_xlo, p_whi, p_wlo, bfx, bx, p_fx, p_xm);

    // 2. logits + softmax -> slice weights (bf16 hi/lo)
    logits_softmax_kernel<<<dim3(NN / 64, BB * HEADS), blk>>>(
        p_xm, Wsl, bsl, temp, p_swhi, p_swlo);

    // 3. slice token split-K partials + reduce
    token_reduce_kernel<<<dim3(SPLITS, BB * HEADS), blk>>>(
        p_swhi, p_swlo, p_fx, p_tokp, p_normp);
    split_reduce_kernel<<<260, 256>>>(p_tokp, p_normp, p_tok, p_norm);

    // 4. tiny attention + fused Wout fold -> Mt (bf16 hi/lo)
    attn_kernel<<<BB * HEADS, blk>>>(p_tok, p_norm, Wq, Wk, Wv, Wout, p_Mthi, p_Mtlo);

    // 5. fused scatter + projection on tensor cores
    final_mma_kernel<<<1024, 256, 65536>>>(p_swhi, p_swlo, p_Mthi, p_Mtlo, bout, out);
}

// round 5
// speedup vs baseline: 3.0101x; 1.2220x over previous
#include <cuda_runtime.h>
#include <cuda_bf16.h>
#include <math.h>
#include <stdint.h>

// Problem constants
#define BB 2
#define HH 256
#define WW 256
#define NN 65536          // H*W
#define CC 128
#define HEADS 8
#define DH 64             // dim_head
#define GG 64             // SLICE
#define INNER 512         // HEADS*DH
#define SPLITS 64         // split-K for token reduction
#define CHUNK 1024        // tokens per split (NN/SPLITS)
#define KTOT 1152         // 9 taps * 128 channels

// ---------------- device scratch (static, no allocs) ----------------
__device__ float g_fx[(size_t)BB * NN * INNER];      // fx_mid  [b][n][inner]
__device__ float g_tokp[(size_t)SPLITS * BB * HEADS * GG * DH];
__device__ float g_normp[(size_t)SPLITS * BB * HEADS * GG];
__device__ float g_tok [(size_t)BB * HEADS * GG * DH];
__device__ float g_norm[(size_t)BB * HEADS * GG];
__device__ float g_lbias[INNER];                     // (bx·Wslice + bslice)/temp

// slice weights as bf16 hi/lo pair  [bh][n][g]
__device__ __align__(16) __nv_bfloat16 g_swhi[(size_t)BB * HEADS * NN * GG];
__device__ __align__(16) __nv_bfloat16 g_swlo[(size_t)BB * HEADS * NN * GG];
// Mt = (out_slice · Wout^T) transposed: [b][o][h*64+g], bf16 hi/lo
__device__ __align__(16) __nv_bfloat16 g_Mthi[(size_t)BB * CC * INNER];
__device__ __align__(16) __nv_bfloat16 g_Mtlo[(size_t)BB * CC * INNER];

// bf16 3-split staging for conv
__device__ __align__(16) __nv_bfloat16 g_xhi[(size_t)BB * NN * CC];
__device__ __align__(16) __nv_bfloat16 g_xlo[(size_t)BB * NN * CC];
// rows 0..511: Wfx cols; rows 512..1023: combined logit weights (Wx·Wslice/temp)
__device__ __align__(16) __nv_bfloat16 g_whi[(size_t)1024 * KTOT];
__device__ __align__(16) __nv_bfloat16 g_wlo[(size_t)1024 * KTOT];

// ---------------- prep kernels ----------------
__global__ void split_x_kernel(const float* __restrict__ x,
                               __nv_bfloat16* __restrict__ xhi,
                               __nv_bfloat16* __restrict__ xlo) {
    size_t i = (size_t)blockIdx.x * 256 + threadIdx.x;
    float f = x[i];
    __nv_bfloat16 h = __float2bfloat16(f);
    float r = f - __bfloat162float(h);
    xhi[i] = h;
    xlo[i] = __float2bfloat16(r);
}

// Wfx (fx conv weights) -> rows 0..511 of g_whi/g_wlo, transposed [oc][k]
__global__ void split_w_kernel(const float* __restrict__ Wfx,
                               __nv_bfloat16* __restrict__ whi,
                               __nv_bfloat16* __restrict__ wlo) {
    int i = blockIdx.x * 256 + threadIdx.x;   // 512*1152 total
    int oc = i / KTOT;
    int k  = i - oc * KTOT;
    float f = Wfx[(size_t)k * 512 + oc];
    __nv_bfloat16 h = __float2bfloat16(f);
    float r = f - __bfloat162float(h);
    whi[i] = h;
    wlo[i] = __float2bfloat16(r);
}

// W~[k][h*64+g] = (sum_d Wx[k][h*64+d]*Wslice[g][d]) / temp_h -> rows 512..1023
__global__ void combine_w_kernel(const float* __restrict__ Wx,
                                 const float* __restrict__ Wsl,
                                 const float* __restrict__ temp,
                                 __nv_bfloat16* __restrict__ whi,
                                 __nv_bfloat16* __restrict__ wlo) {
    __shared__ float ws[64];
    const int col = blockIdx.x;          // 0..511
    const int h = col >> 6, g = col & 63;
    const int tid = threadIdx.x;         // 128
    if (tid < 64) ws[tid] = Wsl[g * 64 + tid];
    __syncthreads();
    float t = fminf(fmaxf(temp[h], 0.1f), 5.0f);
    float invt = 1.0f / t;
    int k = blockIdx.y * 128 + tid;      // 9 y-blocks -> 0..1151
    const float* wr = Wx + (size_t)k * 512 + h * 64;
    float s = 0.f;
    #pragma unroll 8
    for (int d = 0; d < 64; d++) s += wr[d] * ws[d];
    s *= invt;
    __nv_bfloat16 hv = __float2bfloat16(s);
    size_t o = (size_t)(512 + col) * KTOT + k;
    whi[o] = hv;
    wlo[o] = __float2bfloat16(s - __bfloat162float(hv));
}

// lbias[h*64+g] = (bx_h · Wslice_g + bslice_g) / temp_h
__global__ void lbias_kernel(const float* __restrict__ bx,
                             const float* __restrict__ Wsl,
                             const float* __restrict__ bsl,
                             const float* __restrict__ temp,
                             float* __restrict__ lb) {
    int col = threadIdx.x;               // 512
    int h = col >> 6, g = col & 63;
    float t = fminf(fmaxf(temp[h], 0.1f), 5.0f);
    float s = bsl[g];
    #pragma unroll 8
    for (int d = 0; d < 64; d++) s += bx[h * 64 + d] * Wsl[g * 64 + d];
    lb[col] = s / t;
}

// ---------------- shared MMA plumbing ----------------
__device__ __forceinline__ void cp16(uint32_t saddr, const void* g, bool valid) {
    int sz = valid ? 16 : 0;
    asm volatile("cp.async.cg.shared.global [%0], [%1], 16, %2;\n"
                 :: "r"(saddr), "l"(g), "r"(sz));
}

// 16-word rows (final kernel, kc=32 layout)
__device__ __forceinline__ uint32_t lds_frag(const uint32_t* base, int row, int kw) {
    return base[row * 16 + ((((kw >> 2) ^ (row & 3)) << 2) | (kw & 3))];
}
// 32-word rows (conv kernel, kc=64 layout)
__device__ __forceinline__ uint32_t lds32(const uint32_t* base, int row, int kw) {
    return base[row * 32 + ((((kw >> 2) ^ (row & 7)) << 2) | (kw & 3))];
}

__device__ __forceinline__ void mma_bf16(float c[4], uint32_t a0, uint32_t a1,
                                         uint32_t a2, uint32_t a3,
                                         uint32_t b0, uint32_t b1) {
    asm volatile(
        "mma.sync.aligned.m16n8k16.row.col.f32.bf16.bf16.f32 "
        "{%0,%1,%2,%3}, {%4,%5,%6,%7}, {%8,%9}, {%0,%1,%2,%3};"
        : "+f"(c[0]), "+f"(c[1]), "+f"(c[2]), "+f"(c[3])
        : "r"(a0), "r"(a1), "r"(a2), "r"(a3), "r"(b0), "r"(b1));
}

// ---------------- conv as implicit GEMM, kc=64, fused softmax epilogue ----------------
// Block = 128 pixels x 128 cols. ocb 0..3: fx output; ocb 4..7: slice-weight softmax.
// Stage = 64KB: Ahi 16K | Alo 16K | Bhi 16K | Blo 16K (128 rows x 64 bf16, granule swizzle).
#define CSTAGE 65536

__device__ __forceinline__ void conv_load64(
    uint32_t st,
    const __nv_bfloat16* __restrict__ Xhi, const __nv_bfloat16* __restrict__ Xlo,
    const __nv_bfloat16* __restrict__ Whi, const __nv_bfloat16* __restrict__ Wlo,
    int it, int b, int hrow, int w0, int ocb, int tid)
{
    const int kg  = it * 64;
    const int tap = kg >> 7;
    const int dy = tap / 3 - 1, dx = tap % 3 - 1;
    const int c0 = kg & 127;            // 0 or 64
    const int hp = hrow + dy;
    const bool hok = (hp >= 0) && (hp < HH);
    const int hpc = hok ? hp : 0;

    #pragma unroll
    for (int j = 0; j < 16; j++) {
        int id  = tid + j * 256;        // 0..4095
        int arr = id >> 10;             // 0:Ahi 1:Alo 2:Bhi 3:Blo
        int l   = id & 1023;
        int row = l >> 3;               // 0..127
        int gr  = l & 7;                // 16B granule (8 bf16)
        uint32_t saddr = st + arr * 16384 + row * 128 + ((gr ^ (row & 7)) << 4);
        if (arr < 2) {
            int wp = w0 + row + dx;
            bool valid = hok && (wp >= 0) && (wp < WW);
            int wpc = valid ? wp : 0;
            const __nv_bfloat16* g = (arr == 0 ? Xhi : Xlo) +
                (((size_t)b * NN + (size_t)hpc * WW + wpc) * CC + c0 + gr * 8);
            cp16(saddr, g, valid);
        } else {
            const __nv_bfloat16* g = (arr == 2 ? Whi : Wlo) +
                ((size_t)(ocb * 128 + row) * KTOT + kg + gr * 8);
            cp16(saddr, g, true);
        }
    }
}

__global__ __launch_bounds__(256, 1)
void conv_mma_kernel(const __nv_bfloat16* __restrict__ Xhi,
                     const __nv_bfloat16* __restrict__ Xlo,
                     const __nv_bfloat16* __restrict__ Whi,
                     const __nv_bfloat16* __restrict__ Wlo,
                     const float* __restrict__ bfx,
                     const float* __restrict__ lbias,
                     float* __restrict__ ofx,
                     __nv_bfloat16* __restrict__ swhi,
                     __nv_bfloat16* __restrict__ swlo)
{
    extern __shared__ uint32_t smem_u32[];   // 2 stages * 16384 words

    const int ocb = blockIdx.x;              // 0..7
    const int pt  = blockIdx.y;              // 0..511
    const int b   = blockIdx.z;
    const int n0  = pt * 128;
    const int hrow = n0 >> 8;
    const int w0   = n0 & 255;

    const int tid  = threadIdx.x;
    const int wid  = tid >> 5;
    const int lane = tid & 31;
    const int grp  = lane >> 2;
    const int tid4 = lane & 3;
    const int wm   = wid & 1;
    const int wn   = wid >> 1;

    float acc[4][4][4];
    #pragma unroll
    for (int i = 0; i < 4; i++)
        #pragma unroll
        for (int j = 0; j < 4; j++)
            #pragma unroll
            for (int r = 0; r < 4; r++) acc[i][j][r] = 0.f;

    uint32_t sbase = (uint32_t)__cvta_generic_to_shared(smem_u32);

    conv_load64(sbase, Xhi, Xlo, Whi, Wlo, 0, b, hrow, w0, ocb, tid);
    asm volatile("cp.async.commit_group;\n" ::: "memory");

    for (int it = 0; it < 18; ++it) {
        const int cur = it & 1;
        if (it + 1 < 18) {
            conv_load64(sbase + (uint32_t)(1 - cur) * CSTAGE,
                        Xhi, Xlo, Whi, Wlo, it + 1, b, hrow, w0, ocb, tid);
            asm volatile("cp.async.commit_group;\n" ::: "memory");
            asm volatile("cp.async.wait_group 1;\n" ::: "memory");
        } else {
            asm volatile("cp.async.wait_group 0;\n" ::: "memory");
        }
        __syncthreads();

        const uint32_t* Ahi = smem_u32 + (size_t)cur * 16384;
        const uint32_t* Alo = Ahi + 4096;
        const uint32_t* Bhi = Ahi + 8192;
        const uint32_t* Blo = Ahi + 12288;

        #pragma unroll
        for (int s = 0; s < 4; s++) {
            const int kwb = s * 8;
            uint32_t ah[4][4], al[4][4];
            #pragma unroll
            for (int mi = 0; mi < 4; mi++) {
                int r0 = wm * 64 + mi * 16 + grp;
                ah[mi][0] = lds32(Ahi, r0,     kwb + tid4);
                ah[mi][1] = lds32(Ahi, r0 + 8, kwb + tid4);
                ah[mi][2] = lds32(Ahi, r0,     kwb + tid4 + 4);
                ah[mi][3] = lds32(Ahi, r0 + 8, kwb + tid4 + 4);
                al[mi][0] = lds32(Alo, r0,     kwb + tid4);
                al[mi][1] = lds32(Alo, r0 + 8, kwb + tid4);
                al[mi][2] = lds32(Alo, r0,     kwb + tid4 + 4);
                al[mi][3] = lds32(Alo, r0 + 8, kwb + tid4 + 4);
            }
            uint32_t bh[4][2], bl[4][2];
            #pragma unroll
            for (int ni = 0; ni < 4; ni++) {
                int r0 = wn * 32 + ni * 8 + grp;
                bh[ni][0] = lds32(Bhi, r0, kwb + tid4);
                bh[ni][1] = lds32(Bhi, r0, kwb + tid4 + 4);
                bl[ni][0] = lds32(Blo, r0, kwb + tid4);
                bl[ni][1] = lds32(Blo, r0, kwb + tid4 + 4);
            }
            #pragma unroll
            for (int mi = 0; mi < 4; mi++)
                #pragma unroll
                for (int ni = 0; ni < 4; ni++) {
                    mma_bf16(acc[mi][ni], ah[mi][0], ah[mi][1], ah[mi][2], ah[mi][3],
                             bh[ni][0], bh[ni][1]);
                    mma_bf16(acc[mi][ni], ah[mi][0], ah[mi][1], ah[mi][2], ah[mi][3],
                             bl[ni][0], bl[ni][1]);
                    mma_bf16(acc[mi][ni], al[mi][0], al[mi][1], al[mi][2], al[mi][3],
                             bh[ni][0], bh[ni][1]);
                }
        }
        __syncthreads();
    }

    if (ocb < 4) {
        // fx output: direct fp32 stores with bias
        const int ocbase = ocb * 128;
        #pragma unroll
        for (int mi = 0; mi < 4; mi++) {
            int row = wm * 64 + mi * 16 + grp;
            int n  = n0 + row;
            #pragma unroll
            for (int ni = 0; ni < 4; ni++) {
                int col = wn * 32 + ni * 8 + tid4 * 2;
                int oc  = ocbase + col;
                float b0v = bfx[oc], b1v = bfx[oc + 1];
                size_t base0 = ((size_t)b * NN + n) * INNER + oc;
                ofx[base0]     = acc[mi][ni][0] + b0v;
                ofx[base0 + 1] = acc[mi][ni][1] + b1v;
                size_t base1 = ((size_t)b * NN + n + 8) * INNER + oc;
                ofx[base1]     = acc[mi][ni][2] + b0v;
                ofx[base1 + 1] = acc[mi][ni][3] + b1v;
            }
        }
    } else {
        // logits: stage to smem, softmax per (pixel, head), emit bf16 hi/lo
        float* sred = (float*)smem_u32;      // [128][129]
        #pragma unroll
        for (int mi = 0; mi < 4; mi++) {
            int row = wm * 64 + mi * 16 + grp;
            #pragma unroll
            for (int ni = 0; ni < 4; ni++) {
                int col = wn * 32 + ni * 8 + tid4 * 2;
                sred[row * 129 + col]           = acc[mi][ni][0];
                sred[row * 129 + col + 1]       = acc[mi][ni][1];
                sred[(row + 8) * 129 + col]     = acc[mi][ni][2];
                sred[(row + 8) * 129 + col + 1] = acc[mi][ni][3];
            }
        }
        __syncthreads();

        const int row  = tid >> 1;
        const int hloc = tid & 1;
        const int h = (ocb - 4) * 2 + hloc;
        const int n = n0 + row;
        const float* lb = lbias + h * 64;
        float* sr = sred + row * 129 + hloc * 64;

        float mx = -1e30f;
        #pragma unroll 8
        for (int g = 0; g < 64; g++) mx = fmaxf(mx, sr[g] + lb[g]);
        float ssum = 0.f;
        #pragma unroll 8
        for (int g = 0; g < 64; g++) {
            float e = __expf(sr[g] + lb[g] - mx);
            ssum += e;
            sr[g] = e;
        }
        float inv = 1.0f / ssum;

        size_t base = ((size_t)(b * HEADS + h) * NN + n) * GG;
        #pragma unroll
        for (int c = 0; c < 8; c++) {
            union { __nv_bfloat16 hb[8]; uint4 u; } Uh, Ul;
            #pragma unroll
            for (int e = 0; e < 8; e++) {
                float v = sr[c * 8 + e] * inv;
                __nv_bfloat16 hv = __float2bfloat16(v);
                Uh.hb[e] = hv;
                Ul.hb[e] = __float2bfloat16(v - __bfloat162float(hv));
            }
            ((uint4*)(swhi + base))[c] = Uh.u;
            ((uint4*)(swlo + base))[c] = Ul.u;
        }
    }
}

// ---------------- K3: split-K reduction: slice_token partials ----------------
__global__ void token_reduce_kernel(const __nv_bfloat16* __restrict__ whi,
                                    const __nv_bfloat16* __restrict__ wlo,
                                    const float* __restrict__ fx,
                                    float* __restrict__ tokp,
                                    float* __restrict__ normp) {
    const int bh = blockIdx.y;
    const int b = bh >> 3, h = bh & 7;
    const int split = blockIdx.x;
    const int nbase = split * CHUNK;
    const int tx = threadIdx.x, ty = threadIdx.y;
    const int tid = ty * 16 + tx;

    __shared__ float wb[8][64];
    __shared__ float fb[8][64];

    float acc[4][4] = {};
    float nacc[4] = {};

    for (int t0 = 0; t0 < CHUNK; t0 += 8) {
        #pragma unroll
        for (int e = 0; e < 2; e++) {
            int idx = tid + e * 256;
            int t = idx >> 6, q = idx & 63;
            int n = nbase + t0 + t;
            size_t wi = ((size_t)bh * NN + n) * GG + q;
            wb[t][q] = __bfloat162float(whi[wi]) + __bfloat162float(wlo[wi]);
            fb[t][q] = fx[((size_t)b * NN + n) * INNER + h * DH + q];
        }
        __syncthreads();
        #pragma unroll
        for (int t = 0; t < 8; t++) {
            float a[4], bv[4];
            #pragma unroll
            for (int i = 0; i < 4; i++) a[i] = wb[t][ty + 16 * i];
            #pragma unroll
            for (int j = 0; j < 4; j++) bv[j] = fb[t][tx + 16 * j];
            #pragma unroll
            for (int i = 0; i < 4; i++)
                #pragma unroll
                for (int j = 0; j < 4; j++)
                    acc[i][j] += a[i] * bv[j];
            if (tx == 0) {
                #pragma unroll
                for (int i = 0; i < 4; i++) nacc[i] += a[i];
            }
        }
        __syncthreads();
    }

    const size_t base = ((size_t)split * (BB * HEADS) + bh) * (GG * DH);
    #pragma unroll
    for (int i = 0; i < 4; i++)
        #pragma unroll
        for (int j = 0; j < 4; j++)
            tokp[base + (size_t)(ty + 16 * i) * DH + tx + 16 * j] = acc[i][j];
    if (tx == 0) {
        #pragma unroll
        for (int i = 0; i < 4; i++)
            normp[((size_t)split * (BB * HEADS) + bh) * GG + ty + 16 * i] = nacc[i];
    }
}

// ---------------- K3b: deterministic split reduction ----------------
__global__ void split_reduce_kernel(const float* __restrict__ tokp,
                                    const float* __restrict__ normp,
                                    float* __restrict__ tok,
                                    float* __restrict__ norm) {
    const int blk = blockIdx.x;
    const int tid = threadIdx.x;
    if (blk < 256) {
        int idx = blk * 256 + tid;
        float s = 0.f;
        #pragma unroll 8
        for (int sp = 0; sp < SPLITS; sp++)
            s += tokp[(size_t)sp * 65536 + idx];
        tok[idx] = s;
    } else {
        int idx = (blk - 256) * 256 + tid;
        float s = 0.f;
        #pragma unroll 8
        for (int sp = 0; sp < SPLITS; sp++)
            s += normp[(size_t)sp * 1024 + idx];
        norm[idx] = s;
    }
}

// ---------------- K4: tiny attention per (b,h), emits Mt bf16 hi/lo ----------------
__global__ void attn_kernel(const float* __restrict__ tok,
                            const float* __restrict__ norm,
                            const float* __restrict__ Wq,
                            const float* __restrict__ Wk,
                            const float* __restrict__ Wv,
                            const float* __restrict__ Wout,
                            __nv_bfloat16* __restrict__ Mthi,
                            __nv_bfloat16* __restrict__ Mtlo) {
    const int bh = blockIdx.x;
    const int b = bh >> 3, h = bh & 7;
    const int tx = threadIdx.x, ty = threadIdx.y;
    const int tid = ty * 16 + tx;

    __shared__ float A[64][65];
    __shared__ float Bm[64][65];
    __shared__ float Cm[64][65];

    #pragma unroll
    for (int e = 0; e < 16; e++) {
        int idx = tid + e * 256;
        int g = idx >> 6, d = idx & 63;
        A[g][d] = tok[(size_t)bh * 4096 + idx] / (norm[bh * 64 + g] + 1e-5f);
    }
    __syncthreads();

    {
        float aq[4][4] = {}, ak[4][4] = {};
        #pragma unroll
        for (int kk = 0; kk < 64; kk++) {
            float a[4];
            #pragma unroll
            for (int i = 0; i < 4; i++) a[i] = A[ty + 16 * i][kk];
            #pragma unroll
            for (int j = 0; j < 4; j++) {
                float wq = __ldg(&Wq[(tx + 16 * j) * 64 + kk]);
                float wk = __ldg(&Wk[(tx + 16 * j) * 64 + kk]);
                #pragma unroll
                for (int i = 0; i < 4; i++) {
                    aq[i][j] += a[i] * wq;
                    ak[i][j] += a[i] * wk;
                }
            }
        }
        #pragma unroll
        for (int i = 0; i < 4; i++)
            #pragma unroll
            for (int j = 0; j < 4; j++) {
                Bm[ty + 16 * i][tx + 16 * j] = aq[i][j];
                Cm[ty + 16 * i][tx + 16 * j] = ak[i][j];
            }
    }
    __syncthreads();

    {
        float L[4][4] = {};
        #pragma unroll
        for (int kk = 0; kk < 64; kk++) {
            float a[4], bv[4];
            #pragma unroll
            for (int i = 0; i < 4; i++) a[i] = Bm[ty + 16 * i][kk];
            #pragma unroll
            for (int j = 0; j < 4; j++) bv[j] = Cm[tx + 16 * j][kk];
            #pragma unroll
            for (int i = 0; i < 4; i++)
                #pragma unroll
                for (int j = 0; j < 4; j++)
                    L[i][j] += a[i] * bv[j];
        }
        #pragma unroll
        for (int i = 0; i < 4; i++) {
            #pragma unroll
            for (int j = 0; j < 4; j++) L[i][j] *= 0.125f;
            float mx = L[i][0];
            #pragma unroll
            for (int j = 1; j < 4; j++) mx = fmaxf(mx, L[i][j]);
            #pragma unroll
            for (int o = 1; o < 16; o <<= 1)
                mx = fmaxf(mx, __shfl_xor_sync(0xffffffffu, mx, o, 16));
            float s = 0.f;
            #pragma unroll
            for (int j = 0; j < 4; j++) { L[i][j] = __expf(L[i][j] - mx); s += L[i][j]; }
            #pragma unroll
            for (int o = 1; o < 16; o <<= 1)
                s += __shfl_xor_sync(0xffffffffu, s, o, 16);
            float inv = 1.0f / s;
            #pragma unroll
            for (int j = 0; j < 4; j++)
                A[ty + 16 * i][tx + 16 * j] = L[i][j] * inv;
        }
    }
    __syncthreads();

    #pragma unroll
    for (int e = 0; e < 16; e++) {
        int idx = tid + e * 256;
        int g = idx >> 6;
        Bm[g][idx & 63] = tok[(size_t)bh * 4096 + idx] / (norm[bh * 64 + g] + 1e-5f);
    }
    __syncthreads();

    {
        float av[4][4] = {};
        #pragma unroll
        for (int kk = 0; kk < 64; kk++) {
            float a[4];
            #pragma unroll
            for (int i = 0; i < 4; i++) a[i] = Bm[ty + 16 * i][kk];
            #pragma unroll
            for (int j = 0; j < 4; j++) {
                float wv = __ldg(&Wv[(tx + 16 * j) * 64 + kk]);
                #pragma unroll
                for (int i = 0; i < 4; i++) av[i][j] += a[i] * wv;
            }
        }
        __syncthreads();
        #pragma unroll
        for (int i = 0; i < 4; i++)
            #pragma unroll
            for (int j = 0; j < 4; j++)
                Cm[ty + 16 * i][tx + 16 * j] = av[i][j];
    }
    __syncthreads();

    {
        float ao[4][4] = {};
        #pragma unroll
        for (int kk = 0; kk < 64; kk++) {
            float a[4], bv[4];
            #pragma unroll
            for (int i = 0; i < 4; i++) a[i] = A[ty + 16 * i][kk];
            #pragma unroll
            for (int j = 0; j < 4; j++) bv[j] = Cm[kk][tx + 16 * j];
            #pragma unroll
            for (int i = 0; i < 4; i++)
                #pragma unroll
                for (int j = 0; j < 4; j++)
                    ao[i][j] += a[i] * bv[j];
        }
        __syncthreads();
        #pragma unroll
        for (int i = 0; i < 4; i++)
            #pragma unroll
            for (int j = 0; j < 4; j++)
                Bm[ty + 16 * i][tx + 16 * j] = ao[i][j];
    }
    __syncthreads();

    {
        float am[4][8] = {};
        #pragma unroll
        for (int kk = 0; kk < 64; kk++) {
            float a[4];
            #pragma unroll
            for (int i = 0; i < 4; i++) a[i] = Bm[ty + 16 * i][kk];
            #pragma unroll
            for (int j = 0; j < 8; j++) {
                float wv = __ldg(&Wout[(size_t)(tx + 16 * j) * INNER + h * DH + kk]);
                #pragma unroll
                for (int i = 0; i < 4; i++) am[i][j] += a[i] * wv;
            }
        }
        #pragma unroll
        for (int i = 0; i < 4; i++) {
            int g = ty + 16 * i;
            #pragma unroll
            for (int j = 0; j < 8; j++) {
                int o = tx + 16 * j;
                float v = am[i][j];
                __nv_bfloat16 hv = __float2bfloat16(v);
                float r = v - __bfloat162float(hv);
                size_t idx = ((size_t)b * CC + o) * INNER + h * DH + g;
                Mthi[idx] = hv;
                Mtlo[idx] = __float2bfloat16(r);
            }
        }
    }
}

// ---------------- K5: fused scatter + projection on tensor cores ----------------
__global__ __launch_bounds__(256)
void final_mma_kernel(const __nv_bfloat16* __restrict__ Whi,
                      const __nv_bfloat16* __restrict__ Wlo,
                      const __nv_bfloat16* __restrict__ Mthi,
                      const __nv_bfloat16* __restrict__ Mtlo,
                      const float* __restrict__ bout,
                      float* __restrict__ out)
{
    extern __shared__ uint32_t smem_u32[];

    const int pt = blockIdx.x;
    const int b  = pt >> 9;
    const int n0 = (pt & 511) * 128;

    const int tid  = threadIdx.x;
    const int wid  = tid >> 5;
    const int lane = tid & 31;
    const int grp  = lane >> 2;
    const int tid4 = lane & 3;
    const int wm   = wid & 1;
    const int wn   = wid >> 1;

    float acc[4][4][4];
    #pragma unroll
    for (int i = 0; i < 4; i++)
        #pragma unroll
        for (int j = 0; j < 4; j++)
            #pragma unroll
            for (int r = 0; r < 4; r++) acc[i][j][r] = 0.f;

    uint32_t sbase = (uint32_t)__cvta_generic_to_shared(smem_u32);

    auto load_fin = [&](uint32_t sb, int it) {
        const int h  = it >> 1;
        const int g0 = (it & 1) * 32;
        #pragma unroll
        for (int j = 0; j < 8; j++) {
            int id  = tid + j * 256;
            int arr = id >> 9;
            int c   = id & 511;
            int row = c >> 2;
            int c4  = c & 3;
            uint32_t woff = (uint32_t)row * 16 + ((c4 ^ (row & 3)) << 2);
            uint32_t saddr = sb + (arr * 2048 + woff) * 4;
            const __nv_bfloat16* g;
            if (arr < 2) {
                size_t off = (((size_t)(b * HEADS + h) * NN) + n0 + row) * GG + g0 + c4 * 8;
                g = (arr == 0 ? Whi : Wlo) + off;
            } else {
                size_t off = ((size_t)b * CC + row) * INNER + h * DH + g0 + c4 * 8;
                g = (arr == 2 ? Mthi : Mtlo) + off;
            }
            cp16(saddr, g, true);
        }
    };

    load_fin(sbase, 0);
    asm volatile("cp.async.commit_group;\n" ::: "memory");

    for (int it = 0; it < 16; ++it) {
        const int cur = it & 1;
        if (it + 1 < 16) {
            load_fin(sbase + (uint32_t)(1 - cur) * 32768, it + 1);
            asm volatile("cp.async.commit_group;\n" ::: "memory");
            asm volatile("cp.async.wait_group 1;\n" ::: "memory");
        } else {
            asm volatile("cp.async.wait_group 0;\n" ::: "memory");
        }
        __syncthreads();

        const uint32_t* Ahi = smem_u32 + (size_t)cur * 8192;
        const uint32_t* Alo = Ahi + 2048;
        const uint32_t* Bhi = Ahi + 4096;
        const uint32_t* Blo = Ahi + 6144;

        #pragma unroll
        for (int s = 0; s < 2; s++) {
            const int kwb = s * 8;
            uint32_t ah[4][4], al[4][4];
            #pragma unroll
            for (int mi = 0; mi < 4; mi++) {
                int r0 = wm * 64 + mi * 16 + grp;
                ah[mi][0] = lds_frag(Ahi, r0,     kwb + tid4);
                ah[mi][1] = lds_frag(Ahi, r0 + 8, kwb + tid4);
                ah[mi][2] = lds_frag(Ahi, r0,     kwb + tid4 + 4);
                ah[mi][3] = lds_frag(Ahi, r0 + 8, kwb + tid4 + 4);
                al[mi][0] = lds_frag(Alo, r0,     kwb + tid4);
                al[mi][1] = lds_frag(Alo, r0 + 8, kwb + tid4);
                al[mi][2] = lds_frag(Alo, r0,     kwb + tid4 + 4);
                al[mi][3] = lds_frag(Alo, r0 + 8, kwb + tid4 + 4);
            }
            uint32_t bh[4][2], bl[4][2];
            #pragma unroll
            for (int ni = 0; ni < 4; ni++) {
                int r0 = wn * 32 + ni * 8 + grp;
                bh[ni][0] = lds_frag(Bhi, r0, kwb + tid4);
                bh[ni][1] = lds_frag(Bhi, r0, kwb + tid4 + 4);
                bl[ni][0] = lds_frag(Blo, r0, kwb + tid4);
                bl[ni][1] = lds_frag(Blo, r0, kwb + tid4 + 4);
            }
            #pragma unroll
            for (int mi = 0; mi < 4; mi++)
                #pragma unroll
                for (int ni = 0; ni < 4; ni++) {
                    mma_bf16(acc[mi][ni], ah[mi][0], ah[mi][1], ah[mi][2], ah[mi][3],
                             bh[ni][0], bh[ni][1]);
                    mma_bf16(acc[mi][ni], ah[mi][0], ah[mi][1], ah[mi][2], ah[mi][3],
                             bl[ni][0], bl[ni][1]);
                    mma_bf16(acc[mi][ni], al[mi][0], al[mi][1], al[mi][2], al[mi][3],
                             bh[ni][0], bh[ni][1]);
                }
        }
        __syncthreads();
    }

    #pragma unroll
    for (int mi = 0; mi < 4; mi++) {
        int row = wm * 64 + mi * 16 + grp;
        int n  = n0 + row;
        #pragma unroll
        for (int ni = 0; ni < 4; ni++) {
            int oc = wn * 32 + ni * 8 + tid4 * 2;
            float b0v = bout[oc], b1v = bout[oc + 1];
            size_t base0 = ((size_t)b * NN + n) * CC + oc;
            out[base0]     = acc[mi][ni][0] + b0v;
            out[base0 + 1] = acc[mi][ni][1] + b1v;
            size_t base1 = ((size_t)b * NN + n + 8) * CC + oc;
            out[base1]     = acc[mi][ni][2] + b0v;
            out[base1 + 1] = acc[mi][ni][3] + b1v;
        }
    }
}

// ---------------- launch ----------------
extern "C" void kernel_launch(void* const* d_in, const int* in_sizes, int n_in,
                              void* d_out, int out_size) {
    const float* x     = (const float*)d_in[0];
    const float* Wfx   = (const float*)d_in[1];
    const float* bfx   = (const float*)d_in[2];
    const float* Wx    = (const float*)d_in[3];
    const float* bx    = (const float*)d_in[4];
    const float* Wsl   = (const float*)d_in[5];
    const float* bsl   = (const float*)d_in[6];
    const float* temp  = (const float*)d_in[7];
    const float* Wq    = (const float*)d_in[8];
    const float* Wk    = (const float*)d_in[9];
    const float* Wv    = (const float*)d_in[10];
    const float* Wout  = (const float*)d_in[11];
    const float* bout  = (const float*)d_in[12];
    float* out = (float*)d_out;

    float *p_fx, *p_tokp, *p_normp, *p_tok, *p_norm, *p_lb;
    __nv_bfloat16 *p_xhi, *p_xlo, *p_whi, *p_wlo;
    __nv_bfloat16 *p_swhi, *p_swlo, *p_Mthi, *p_Mtlo;
    cudaGetSymbolAddress((void**)&p_fx, g_fx);
    cudaGetSymbolAddress((void**)&p_tokp, g_tokp);
    cudaGetSymbolAddress((void**)&p_normp, g_normp);
    cudaGetSymbolAddress((void**)&p_tok, g_tok);
    cudaGetSymbolAddress((void**)&p_norm, g_norm);
    cudaGetSymbolAddress((void**)&p_lb, g_lbias);
    cudaGetSymbolAddress((void**)&p_xhi, g_xhi);
    cudaGetSymbolAddress((void**)&p_xlo, g_xlo);
    cudaGetSymbolAddress((void**)&p_whi, g_whi);
    cudaGetSymbolAddress((void**)&p_wlo, g_wlo);
    cudaGetSymbolAddress((void**)&p_swhi, g_swhi);
    cudaGetSymbolAddress((void**)&p_swlo, g_swlo);
    cudaGetSymbolAddress((void**)&p_Mthi, g_Mthi);
    cudaGetSymbolAddress((void**)&p_Mtlo, g_Mtlo);

    static bool attr_set = false;
    if (!attr_set) {
        cudaFuncSetAttribute(conv_mma_kernel,
                             cudaFuncAttributeMaxDynamicSharedMemorySize, 2 * CSTAGE);
        cudaFuncSetAttribute(final_mma_kernel,
                             cudaFuncAttributeMaxDynamicSharedMemorySize, 65536);
        attr_set = true;
    }

    dim3 blk(16, 16);

    // 0. staging: x split, fx weights split, combined logit weights, logit bias
    split_x_kernel<<<(BB * NN * CC) / 256, 256>>>(x, p_xhi, p_xlo);
    split_w_kernel<<<(512 * KTOT) / 256, 256>>>(Wfx, p_whi, p_wlo);
    combine_w_kernel<<<dim3(512, 9), 128>>>(Wx, Wsl, temp, p_whi, p_wlo);
    lbias_kernel<<<1, 512>>>(bx, Wsl, bsl, temp, p_lb);

    // 1. fused conv: fx (ocb 0-3) + slice-weight softmax (ocb 4-7)
    conv_mma_kernel<<<dim3(8, 512, BB), 256, 2 * CSTAGE>>>(
        p_xhi, p_xlo, p_whi, p_wlo, bfx, p_lb, p_fx, p_swhi, p_swlo);

    // 2. slice token split-K partials + reduce
    token_reduce_kernel<<<dim3(SPLITS, BB * HEADS), blk>>>(
        p_swhi, p_swlo, p_fx, p_tokp, p_normp);
    split_reduce_kernel<<<260, 256>>>(p_tokp, p_normp, p_tok, p_norm);

    // 3. tiny attention + fused Wout fold -> Mt (bf16 hi/lo)
    attn_kernel<<<BB * HEADS, blk>>>(p_tok, p_norm, Wq, Wk, Wv, Wout, p_Mthi, p_Mtlo);

    // 4. fused scatter + projection on tensor cores
    final_mma_kernel<<<1024, 256, 65536>>>(p_swhi, p_swlo, p_Mthi, p_Mtlo, bout, out);
}

// round 6
// speedup vs baseline: 3.2406x; 1.0766x over previous
#include <cuda_runtime.h>
#include <cuda_bf16.h>
#include <math.h>
#include <stdint.h>

// Problem constants
#define BB 2
#define HH 256
#define WW 256
#define NN 65536          // H*W
#define CC 128
#define HEADS 8
#define DH 64             // dim_head
#define GG 64             // SLICE
#define INNER 512         // HEADS*DH
#define SPLITS 64         // split-K for token reduction
#define CHUNK 1024        // tokens per split (NN/SPLITS)
#define KTOT 1152         // 9 taps * 128 channels

// ---------------- device scratch (static, no allocs) ----------------
__device__ float g_fx[(size_t)BB * NN * INNER];      // fx_mid  [b][n][inner]
__device__ float g_tokp[(size_t)SPLITS * BB * HEADS * GG * DH];
__device__ float g_normp[(size_t)SPLITS * BB * HEADS * GG];
__device__ float g_tok [(size_t)BB * HEADS * GG * DH];
__device__ float g_norm[(size_t)BB * HEADS * GG];
__device__ float g_lbias[INNER];                     // (bx·Wslice + bslice)/temp

// slice weights as bf16 hi/lo pair  [bh][n][g]
__device__ __align__(16) __nv_bfloat16 g_swhi[(size_t)BB * HEADS * NN * GG];
__device__ __align__(16) __nv_bfloat16 g_swlo[(size_t)BB * HEADS * NN * GG];
// Mt = (out_slice · Wout^T) transposed: [b][o][h*64+g], bf16 hi/lo
__device__ __align__(16) __nv_bfloat16 g_Mthi[(size_t)BB * CC * INNER];
__device__ __align__(16) __nv_bfloat16 g_Mtlo[(size_t)BB * CC * INNER];

// bf16 3-split staging for conv
__device__ __align__(16) __nv_bfloat16 g_xhi[(size_t)BB * NN * CC];
__device__ __align__(16) __nv_bfloat16 g_xlo[(size_t)BB * NN * CC];
// rows 0..511: Wfx cols; rows 512..1023: combined logit weights (Wx·Wslice/temp)
__device__ __align__(16) __nv_bfloat16 g_whi[(size_t)1024 * KTOT];
__device__ __align__(16) __nv_bfloat16 g_wlo[(size_t)1024 * KTOT];

// ---------------- prep kernels ----------------
__global__ void split_x_kernel(const float* __restrict__ x,
                               __nv_bfloat16* __restrict__ xhi,
                               __nv_bfloat16* __restrict__ xlo) {
    size_t i = (size_t)blockIdx.x * 256 + threadIdx.x;
    float f = x[i];
    __nv_bfloat16 h = __float2bfloat16(f);
    float r = f - __bfloat162float(h);
    xhi[i] = h;
    xlo[i] = __float2bfloat16(r);
}

// Wfx (fx conv weights) -> rows 0..511 of g_whi/g_wlo, transposed [oc][k]
__global__ void split_w_kernel(const float* __restrict__ Wfx,
                               __nv_bfloat16* __restrict__ whi,
                               __nv_bfloat16* __restrict__ wlo) {
    int i = blockIdx.x * 256 + threadIdx.x;   // 512*1152 total
    int oc = i / KTOT;
    int k  = i - oc * KTOT;
    float f = Wfx[(size_t)k * 512 + oc];
    __nv_bfloat16 h = __float2bfloat16(f);
    float r = f - __bfloat162float(h);
    whi[i] = h;
    wlo[i] = __float2bfloat16(r);
}

// W~[k][h*64+g] = (sum_d Wx[k][h*64+d]*Wslice[g][d]) / temp_h -> rows 512..1023
__global__ void combine_w_kernel(const float* __restrict__ Wx,
                                 const float* __restrict__ Wsl,
                                 const float* __restrict__ temp,
                                 __nv_bfloat16* __restrict__ whi,
                                 __nv_bfloat16* __restrict__ wlo) {
    __shared__ float ws[64];
    const int col = blockIdx.x;          // 0..511
    const int h = col >> 6, g = col & 63;
    const int tid = threadIdx.x;         // 128
    if (tid < 64) ws[tid] = Wsl[g * 64 + tid];
    __syncthreads();
    float t = fminf(fmaxf(temp[h], 0.1f), 5.0f);
    float invt = 1.0f / t;
    int k = blockIdx.y * 128 + tid;      // 9 y-blocks -> 0..1151
    const float* wr = Wx + (size_t)k * 512 + h * 64;
    float s = 0.f;
    #pragma unroll 8
    for (int d = 0; d < 64; d++) s += wr[d] * ws[d];
    s *= invt;
    __nv_bfloat16 hv = __float2bfloat16(s);
    size_t o = (size_t)(512 + col) * KTOT + k;
    whi[o] = hv;
    wlo[o] = __float2bfloat16(s - __bfloat162float(hv));
}

// lbias[h*64+g] = (bx_h · Wslice_g + bslice_g) / temp_h   (one block per col)
__global__ void lbias_kernel(const float* __restrict__ bx,
                             const float* __restrict__ Wsl,
                             const float* __restrict__ bsl,
                             const float* __restrict__ temp,
                             float* __restrict__ lb) {
    int col = blockIdx.x;                // 0..511
    int h = col >> 6, g = col & 63;
    int lane = threadIdx.x;              // 32
    float s = bx[h * 64 + lane] * Wsl[g * 64 + lane]
            + bx[h * 64 + 32 + lane] * Wsl[g * 64 + 32 + lane];
    #pragma unroll
    for (int o = 16; o > 0; o >>= 1)
        s += __shfl_xor_sync(0xffffffffu, s, o);
    if (lane == 0) {
        float t = fminf(fmaxf(temp[h], 0.1f), 5.0f);
        lb[col] = (s + bsl[g]) / t;
    }
}

// ---------------- shared MMA plumbing ----------------
__device__ __forceinline__ void cp16(uint32_t saddr, const void* g, bool valid) {
    int sz = valid ? 16 : 0;
    asm volatile("cp.async.cg.shared.global [%0], [%1], 16, %2;\n"
                 :: "r"(saddr), "l"(g), "r"(sz));
}

// 16-word rows (final kernel, kc=32 layout)
__device__ __forceinline__ uint32_t lds_frag(const uint32_t* base, int row, int kw) {
    return base[row * 16 + ((((kw >> 2) ^ (row & 3)) << 2) | (kw & 3))];
}

__device__ __forceinline__ void mma_bf16(float c[4], uint32_t a0, uint32_t a1,
                                         uint32_t a2, uint32_t a3,
                                         uint32_t b0, uint32_t b1) {
    asm volatile(
        "mma.sync.aligned.m16n8k16.row.col.f32.bf16.bf16.f32 "
        "{%0,%1,%2,%3}, {%4,%5,%6,%7}, {%8,%9}, {%0,%1,%2,%3};"
        : "+f"(c[0]), "+f"(c[1]), "+f"(c[2]), "+f"(c[3])
        : "r"(a0), "r"(a1), "r"(a2), "r"(a3), "r"(b0), "r"(b1));
}

__device__ __forceinline__ void ldsm4(uint32_t r[4], uint32_t addr) {
    asm volatile("ldmatrix.sync.aligned.m8n8.x4.shared.b16 {%0,%1,%2,%3}, [%4];"
                 : "=r"(r[0]), "=r"(r[1]), "=r"(r[2]), "=r"(r[3]) : "r"(addr));
}

// ---------------- conv: implicit GEMM 128x256, kc=64, ldmatrix feed ----------------
// ocb 0..1: fx output (cols ocb*256..+255); ocb 2..3: slice-weight softmax (4 heads each).
// Stage (96KB): Ahi 16K | Alo 16K | Bhi 32K | Blo 32K.
// Rows are 128B (64 bf16), granule-swizzled: off = row*128 + ((gr ^ (row&7))<<4).
#define CSTAGE 98304

__device__ __forceinline__ void conv_load(
    uint32_t st,
    const __nv_bfloat16* __restrict__ Xhi, const __nv_bfloat16* __restrict__ Xlo,
    const __nv_bfloat16* __restrict__ Whi, const __nv_bfloat16* __restrict__ Wlo,
    int it, int b, int hrow, int w0, int ocb, int tid)
{
    const int kg  = it * 64;
    const int tap = kg >> 7;
    const int dy = tap / 3 - 1, dx = tap % 3 - 1;
    const int c0 = kg & 127;            // 0 or 64
    const int hp = hrow + dy;
    const bool hok = (hp >= 0) && (hp < HH);
    const int hpc = hok ? hp : 0;

    // A: 2 arrays x 128 rows x 8 granules = 2048 lines (j = 0..7)
    #pragma unroll
    for (int j = 0; j < 8; j++) {
        int id  = tid + j * 256;
        int arr = id >> 10;             // 0:Ahi 1:Alo
        int l   = id & 1023;
        int row = l >> 3;
        int gr  = l & 7;
        uint32_t saddr = st + arr * 16384 + row * 128 + ((gr ^ (row & 7)) << 4);
        int wp = w0 + row + dx;
        bool valid = hok && (wp >= 0) && (wp < WW);
        int wpc = valid ? wp : 0;
        const __nv_bfloat16* g = (arr == 0 ? Xhi : Xlo) +
            (((size_t)b * NN + (size_t)hpc * WW + wpc) * CC + c0 + gr * 8);
        cp16(saddr, g, valid);
    }
    // B: 2 arrays x 256 rows x 8 granules = 4096 lines (j = 8..23)
    #pragma unroll
    for (int j = 8; j < 24; j++) {
        int id  = tid + (j - 8) * 256;  // 0..4095
        int arr = id >> 11;             // 0:Bhi 1:Blo
        int l   = id & 2047;
        int row = l >> 3;
        int gr  = l & 7;
        uint32_t saddr = st + 32768 + arr * 32768 + row * 128 + ((gr ^ (row & 7)) << 4);
        const __nv_bfloat16* g = (arr == 0 ? Whi : Wlo) +
            ((size_t)(ocb * 256 + row) * KTOT + kg + gr * 8);
        cp16(saddr, g, true);
    }
}

__global__ __launch_bounds__(256, 1)
void conv_mma_kernel(const __nv_bfloat16* __restrict__ Xhi,
                     const __nv_bfloat16* __restrict__ Xlo,
                     const __nv_bfloat16* __restrict__ Whi,
                     const __nv_bfloat16* __restrict__ Wlo,
                     const float* __restrict__ bfx,
                     const float* __restrict__ lbias,
                     float* __restrict__ ofx,
                     __nv_bfloat16* __restrict__ swhi,
                     __nv_bfloat16* __restrict__ swlo)
{
    extern __shared__ char smem[];           // 2 stages x 96KB

    const int ocb = blockIdx.x;              // 0..3
    const int pt  = blockIdx.y;              // 0..511
    const int b   = blockIdx.z;
    const int n0  = pt * 128;
    const int hrow = n0 >> 8;
    const int w0   = n0 & 255;

    const int tid  = threadIdx.x;
    const int wid  = tid >> 5;
    const int lane = tid & 31;
    const int grp  = lane >> 2;
    const int tid4 = lane & 3;
    const int wm   = wid & 1;                // 2 row-groups of 64
    const int wn   = wid >> 1;               // 4 col-groups of 64

    // ldmatrix lane addressing precompute
    const int t8   = lane >> 3;              // tile index 0..3
    const int r8   = lane & 7;               // row within tile
    const int a_roff = ((t8 & 1) << 3) + r8; // A: +0/+8 rows, granule pair t8>>1
    const int a_gsel = t8 >> 1;
    const int b_roff = ((t8 >> 1) << 3) + r8;// B: +0/+8 rows, granule pair t8&1
    const int b_gsel = t8 & 1;

    float acc[4][8][4];
    #pragma unroll
    for (int i = 0; i < 4; i++)
        #pragma unroll
        for (int j = 0; j < 8; j++)
            #pragma unroll
            for (int r = 0; r < 4; r++) acc[i][j][r] = 0.f;

    uint32_t sbase = (uint32_t)__cvta_generic_to_shared(smem);

    conv_load(sbase, Xhi, Xlo, Whi, Wlo, 0, b, hrow, w0, ocb, tid);
    asm volatile("cp.async.commit_group;\n" ::: "memory");

    for (int it = 0; it < 18; ++it) {
        const int cur = it & 1;
        if (it + 1 < 18) {
            conv_load(sbase + (uint32_t)(1 - cur) * CSTAGE,
                      Xhi, Xlo, Whi, Wlo, it + 1, b, hrow, w0, ocb, tid);
            asm volatile("cp.async.commit_group;\n" ::: "memory");
            asm volatile("cp.async.wait_group 1;\n" ::: "memory");
        } else {
            asm volatile("cp.async.wait_group 0;\n" ::: "memory");
        }
        __syncthreads();

        const uint32_t stA = sbase + (uint32_t)cur * CSTAGE;
        const uint32_t stB = stA + 32768;

        #pragma unroll
        for (int s = 0; s < 4; s++) {
            // A fragments: 4 mi x (hi, lo)
            uint32_t ah[4][4], al[4][4];
            #pragma unroll
            for (int mi = 0; mi < 4; mi++) {
                int row = wm * 64 + mi * 16 + a_roff;
                int g = 2 * s + a_gsel;
                uint32_t addr = stA + row * 128 + ((g ^ (row & 7)) << 4);
                ldsm4(ah[mi], addr);
                ldsm4(al[mi], addr + 16384);
            }
            // B fragments per 16-col pair, then MMAs
            #pragma unroll
            for (int np = 0; np < 4; np++) {
                int row = wn * 64 + np * 16 + b_roff;
                int g = 2 * s + b_gsel;
                uint32_t addr = stB + row * 128 + ((g ^ (row & 7)) << 4);
                uint32_t bh[4], bl[4];
                ldsm4(bh, addr);
                ldsm4(bl, addr + 32768);
                #pragma unroll
                for (int mi = 0; mi < 4; mi++) {
                    float* c0 = acc[mi][2 * np];
                    float* c1 = acc[mi][2 * np + 1];
                    mma_bf16(c0, ah[mi][0], ah[mi][1], ah[mi][2], ah[mi][3], bh[0], bh[1]);
                    mma_bf16(c0, ah[mi][0], ah[mi][1], ah[mi][2], ah[mi][3], bl[0], bl[1]);
                    mma_bf16(c0, al[mi][0], al[mi][1], al[mi][2], al[mi][3], bh[0], bh[1]);
                    mma_bf16(c1, ah[mi][0], ah[mi][1], ah[mi][2], ah[mi][3], bh[2], bh[3]);
                    mma_bf16(c1, ah[mi][0], ah[mi][1], ah[mi][2], ah[mi][3], bl[2], bl[3]);
                    mma_bf16(c1, al[mi][0], al[mi][1], al[mi][2], al[mi][3], bh[2], bh[3]);
                }
            }
        }
        __syncthreads();
    }

    if (ocb < 2) {
        // fx output: direct fp32 stores with bias
        const int ocbase = ocb * 256;
        #pragma unroll
        for (int mi = 0; mi < 4; mi++) {
            int row = wm * 64 + mi * 16 + grp;
            int n  = n0 + row;
            #pragma unroll
            for (int ni = 0; ni < 8; ni++) {
                int col = wn * 64 + ni * 8 + tid4 * 2;
                int oc  = ocbase + col;
                float b0v = bfx[oc], b1v = bfx[oc + 1];
                size_t base0 = ((size_t)b * NN + n) * INNER + oc;
                ofx[base0]     = acc[mi][ni][0] + b0v;
                ofx[base0 + 1] = acc[mi][ni][1] + b1v;
                size_t base1 = ((size_t)b * NN + n + 8) * INNER + oc;
                ofx[base1]     = acc[mi][ni][2] + b0v;
                ofx[base1 + 1] = acc[mi][ni][3] + b1v;
            }
        }
    } else {
        // logits: stage to smem, softmax per (pixel, head), emit bf16 hi/lo
        float* sred = (float*)smem;          // [128][260]
        #pragma unroll
        for (int mi = 0; mi < 4; mi++) {
            int row = wm * 64 + mi * 16 + grp;
            #pragma unroll
            for (int ni = 0; ni < 8; ni++) {
                int col = wn * 64 + ni * 8 + tid4 * 2;
                sred[row * 260 + col]           = acc[mi][ni][0];
                sred[row * 260 + col + 1]       = acc[mi][ni][1];
                sred[(row + 8) * 260 + col]     = acc[mi][ni][2];
                sred[(row + 8) * 260 + col + 1] = acc[mi][ni][3];
            }
        }
        __syncthreads();

        #pragma unroll
        for (int pass = 0; pass < 2; pass++) {
            int tsk = tid + pass * 256;      // 0..511
            int row  = tsk >> 2;
            int hloc = tsk & 3;
            int h = (ocb - 2) * 4 + hloc;
            int n = n0 + row;
            const float* lb = lbias + h * 64;
            float* sr = sred + row * 260 + hloc * 64;

            float mx = -1e30f;
            #pragma unroll 8
            for (int g = 0; g < 64; g++) mx = fmaxf(mx, sr[g] + lb[g]);
            float ssum = 0.f;
            #pragma unroll 8
            for (int g = 0; g < 64; g++) {
                float e = __expf(sr[g] + lb[g] - mx);
                ssum += e;
                sr[g] = e;
            }
            float inv = 1.0f / ssum;

            size_t base = ((size_t)(b * HEADS + h) * NN + n) * GG;
            #pragma unroll
            for (int c = 0; c < 8; c++) {
                union { __nv_bfloat16 hb[8]; uint4 u; } Uh, Ul;
                #pragma unroll
                for (int e = 0; e < 8; e++) {
                    float v = sr[c * 8 + e] * inv;
                    __nv_bfloat16 hv = __float2bfloat16(v);
                    Uh.hb[e] = hv;
                    Ul.hb[e] = __float2bfloat16(v - __bfloat162float(hv));
                }
                ((uint4*)(swhi + base))[c] = Uh.u;
                ((uint4*)(swlo + base))[c] = Ul.u;
            }
        }
    }
}

// ---------------- K3: split-K reduction: slice_token partials ----------------
__global__ void token_reduce_kernel(const __nv_bfloat16* __restrict__ whi,
                                    const __nv_bfloat16* __restrict__ wlo,
                                    const float* __restrict__ fx,
                                    float* __restrict__ tokp,
                                    float* __restrict__ normp) {
    const int bh = blockIdx.y;
    const int b = bh >> 3, h = bh & 7;
    const int split = blockIdx.x;
    const int nbase = split * CHUNK;
    const int tx = threadIdx.x, ty = threadIdx.y;
    const int tid = ty * 16 + tx;

    __shared__ float wb[8][64];
    __shared__ float fb[8][64];

    float acc[4][4] = {};
    float nacc[4] = {};

    for (int t0 = 0; t0 < CHUNK; t0 += 8) {
        #pragma unroll
        for (int e = 0; e < 2; e++) {
            int idx = tid + e * 256;
            int t = idx >> 6, q = idx & 63;
            int n = nbase + t0 + t;
            size_t wi = ((size_t)bh * NN + n) * GG + q;
            wb[t][q] = __bfloat162float(whi[wi]) + __bfloat162float(wlo[wi]);
            fb[t][q] = fx[((size_t)b * NN + n) * INNER + h * DH + q];
        }
        __syncthreads();
        #pragma unroll
        for (int t = 0; t < 8; t++) {
            float a[4], bv[4];
            #pragma unroll
            for (int i = 0; i < 4; i++) a[i] = wb[t][ty + 16 * i];
            #pragma unroll
            for (int j = 0; j < 4; j++) bv[j] = fb[t][tx + 16 * j];
            #pragma unroll
            for (int i = 0; i < 4; i++)
                #pragma unroll
                for (int j = 0; j < 4; j++)
                    acc[i][j] += a[i] * bv[j];
            if (tx == 0) {
                #pragma unroll
                for (int i = 0; i < 4; i++) nacc[i] += a[i];
            }
        }
        __syncthreads();
    }

    const size_t base = ((size_t)split * (BB * HEADS) + bh) * (GG * DH);
    #pragma unroll
    for (int i = 0; i < 4; i++)
        #pragma unroll
        for (int j = 0; j < 4; j++)
            tokp[base + (size_t)(ty + 16 * i) * DH + tx + 16 * j] = acc[i][j];
    if (tx == 0) {
        #pragma unroll
        for (int i = 0; i < 4; i++)
            normp[((size_t)split * (BB * HEADS) + bh) * GG + ty + 16 * i] = nacc[i];
    }
}

// ---------------- K3b: deterministic split reduction ----------------
__global__ void split_reduce_kernel(const float* __restrict__ tokp,
                                    const float* __restrict__ normp,
                                    float* __restrict__ tok,
                                    float* __restrict__ norm) {
    const int blk = blockIdx.x;
    const int tid = threadIdx.x;
    if (blk < 256) {
        int idx = blk * 256 + tid;
        float s = 0.f;
        #pragma unroll 8
        for (int sp = 0; sp < SPLITS; sp++)
            s += tokp[(size_t)sp * 65536 + idx];
        tok[idx] = s;
    } else {
        int idx = (blk - 256) * 256 + tid;
        float s = 0.f;
        #pragma unroll 8
        for (int sp = 0; sp < SPLITS; sp++)
            s += normp[(size_t)sp * 1024 + idx];
        norm[idx] = s;
    }
}

// ---------------- K4: tiny attention per (b,h), emits Mt bf16 hi/lo ----------------
__global__ void attn_kernel(const float* __restrict__ tok,
                            const float* __restrict__ norm,
                            const float* __restrict__ Wq,
                            const float* __restrict__ Wk,
                            const float* __restrict__ Wv,
                            const float* __restrict__ Wout,
                            __nv_bfloat16* __restrict__ Mthi,
                            __nv_bfloat16* __restrict__ Mtlo) {
    const int bh = blockIdx.x;
    const int b = bh >> 3, h = bh & 7;
    const int tx = threadIdx.x, ty = threadIdx.y;
    const int tid = ty * 16 + tx;

    __shared__ float A[64][65];
    __shared__ float Bm[64][65];
    __shared__ float Cm[64][65];

    #pragma unroll
    for (int e = 0; e < 16; e++) {
        int idx = tid + e * 256;
        int g = idx >> 6, d = idx & 63;
        A[g][d] = tok[(size_t)bh * 4096 + idx] / (norm[bh * 64 + g] + 1e-5f);
    }
    __syncthreads();

    {
        float aq[4][4] = {}, ak[4][4] = {};
        #pragma unroll
        for (int kk = 0; kk < 64; kk++) {
            float a[4];
            #pragma unroll
            for (int i = 0; i < 4; i++) a[i] = A[ty + 16 * i][kk];
            #pragma unroll
            for (int j = 0; j < 4; j++) {
                float wq = __ldg(&Wq[(tx + 16 * j) * 64 + kk]);
                float wk = __ldg(&Wk[(tx + 16 * j) * 64 + kk]);
                #pragma unroll
                for (int i = 0; i < 4; i++) {
                    aq[i][j] += a[i] * wq;
                    ak[i][j] += a[i] * wk;
                }
            }
        }
        #pragma unroll
        for (int i = 0; i < 4; i++)
            #pragma unroll
            for (int j = 0; j < 4; j++) {
                Bm[ty + 16 * i][tx + 16 * j] = aq[i][j];
                Cm[ty + 16 * i][tx + 16 * j] = ak[i][j];
            }
    }
    __syncthreads();

    {
        float L[4][4] = {};
        #pragma unroll
        for (int kk = 0; kk < 64; kk++) {
            float a[4], bv[4];
            #pragma unroll
            for (int i = 0; i < 4; i++) a[i] = Bm[ty + 16 * i][kk];
            #pragma unroll
            for (int j = 0; j < 4; j++) bv[j] = Cm[tx + 16 * j][kk];
            #pragma unroll
            for (int i = 0; i < 4; i++)
                #pragma unroll
                for (int j = 0; j < 4; j++)
                    L[i][j] += a[i] * bv[j];
        }
        #pragma unroll
        for (int i = 0; i < 4; i++) {
            #pragma unroll
            for (int j = 0; j < 4; j++) L[i][j] *= 0.125f;
            float mx = L[i][0];
            #pragma unroll
            for (int j = 1; j < 4; j++) mx = fmaxf(mx, L[i][j]);
            #pragma unroll
            for (int o = 1; o < 16; o <<= 1)
                mx = fmaxf(mx, __shfl_xor_sync(0xffffffffu, mx, o, 16));
            float s = 0.f;
            #pragma unroll
            for (int j = 0; j < 4; j++) { L[i][j] = __expf(L[i][j] - mx); s += L[i][j]; }
            #pragma unroll
            for (int o = 1; o < 16; o <<= 1)
                s += __shfl_xor_sync(0xffffffffu, s, o, 16);
            float inv = 1.0f / s;
            #pragma unroll
            for (int j = 0; j < 4; j++)
                A[ty + 16 * i][tx + 16 * j] = L[i][j] * inv;
        }
    }
    __syncthreads();

    #pragma unroll
    for (int e = 0; e < 16; e++) {
        int idx = tid + e * 256;
        int g = idx >> 6;
        Bm[g][idx & 63] = tok[(size_t)bh * 4096 + idx] / (norm[bh * 64 + g] + 1e-5f);
    }
    __syncthreads();

    {
        float av[4][4] = {};
        #pragma unroll
        for (int kk = 0; kk < 64; kk++) {
            float a[4];
            #pragma unroll
            for (int i = 0; i < 4; i++) a[i] = Bm[ty + 16 * i][kk];
            #pragma unroll
            for (int j = 0; j < 4; j++) {
                float wv = __ldg(&Wv[(tx + 16 * j) * 64 + kk]);
                #pragma unroll
                for (int i = 0; i < 4; i++) av[i][j] += a[i] * wv;
            }
        }
        __syncthreads();
        #pragma unroll
        for (int i = 0; i < 4; i++)
            #pragma unroll
            for (int j = 0; j < 4; j++)
                Cm[ty + 16 * i][tx + 16 * j] = av[i][j];
    }
    __syncthreads();

    {
        float ao[4][4] = {};
        #pragma unroll
        for (int kk = 0; kk < 64; kk++) {
            float a[4], bv[4];
            #pragma unroll
            for (int i = 0; i < 4; i++) a[i] = A[ty + 16 * i][kk];
            #pragma unroll
            for (int j = 0; j < 4; j++) bv[j] = Cm[kk][tx + 16 * j];
            #pragma unroll
            for (int i = 0; i < 4; i++)
                #pragma unroll
                for (int j = 0; j < 4; j++)
                    ao[i][j] += a[i] * bv[j];
        }
        __syncthreads();
        #pragma unroll
        for (int i = 0; i < 4; i++)
            #pragma unroll
            for (int j = 0; j < 4; j++)
                Bm[ty + 16 * i][tx + 16 * j] = ao[i][j];
    }
    __syncthreads();

    {
        float am[4][8] = {};
        #pragma unroll
        for (int kk = 0; kk < 64; kk++) {
            float a[4];
            #pragma unroll
            for (int i = 0; i < 4; i++) a[i] = Bm[ty + 16 * i][kk];
            #pragma unroll
            for (int j = 0; j < 8; j++) {
                float wv = __ldg(&Wout[(size_t)(tx + 16 * j) * INNER + h * DH + kk]);
                #pragma unroll
                for (int i = 0; i < 4; i++) am[i][j] += a[i] * wv;
            }
        }
        #pragma unroll
        for (int i = 0; i < 4; i++) {
            int g = ty + 16 * i;
            #pragma unroll
            for (int j = 0; j < 8; j++) {
                int o = tx + 16 * j;
                float v = am[i][j];
                __nv_bfloat16 hv = __float2bfloat16(v);
                float r = v - __bfloat162float(hv);
                size_t idx = ((size_t)b * CC + o) * INNER + h * DH + g;
                Mthi[idx] = hv;
                Mtlo[idx] = __float2bfloat16(r);
            }
        }
    }
}

// ---------------- K5: fused scatter + projection on tensor cores ----------------
__global__ __launch_bounds__(256)
void final_mma_kernel(const __nv_bfloat16* __restrict__ Whi,
                      const __nv_bfloat16* __restrict__ Wlo,
                      const __nv_bfloat16* __restrict__ Mthi,
                      const __nv_bfloat16* __restrict__ Mtlo,
                      const float* __restrict__ bout,
                      float* __restrict__ out)
{
    extern __shared__ uint32_t smem_u32[];

    const int pt = blockIdx.x;
    const int b  = pt >> 9;
    const int n0 = (pt & 511) * 128;

    const int tid  = threadIdx.x;
    const int wid  = tid >> 5;
    const int lane = tid & 31;
    const int grp  = lane >> 2;
    const int tid4 = lane & 3;
    const int wm   = wid & 1;
    const int wn   = wid >> 1;

    float acc[4][4][4];
    #pragma unroll
    for (int i = 0; i < 4; i++)
        #pragma unroll
        for (int j = 0; j < 4; j++)
            #pragma unroll
            for (int r = 0; r < 4; r++) acc[i][j][r] = 0.f;

    uint32_t sbase = (uint32_t)__cvta_generic_to_shared(smem_u32);

    auto load_fin = [&](uint32_t sb, int it) {
        const int h  = it >> 1;
        const int g0 = (it & 1) * 32;
        #pragma unroll
        for (int j = 0; j < 8; j++) {
            int id  = tid + j * 256;
            int arr = id >> 9;
            int c   = id & 511;
            int row = c >> 2;
            int c4  = c & 3;
            uint32_t woff = (uint32_t)row * 16 + ((c4 ^ (row & 3)) << 2);
            uint32_t saddr = sb + (arr * 2048 + woff) * 4;
            const __nv_bfloat16* g;
            if (arr < 2) {
                size_t off = (((size_t)(b * HEADS + h) * NN) + n0 + row) * GG + g0 + c4 * 8;
                g = (arr == 0 ? Whi : Wlo) + off;
            } else {
                size_t off = ((size_t)b * CC + row) * INNER + h * DH + g0 + c4 * 8;
                g = (arr == 2 ? Mthi : Mtlo) + off;
            }
            cp16(saddr, g, true);
        }
    };

    load_fin(sbase, 0);
    asm volatile("cp.async.commit_group;\n" ::: "memory");

    for (int it = 0; it < 16; ++it) {
        const int cur = it & 1;
        if (it + 1 < 16) {
            load_fin(sbase + (uint32_t)(1 - cur) * 32768, it + 1);
            asm volatile("cp.async.commit_group;\n" ::: "memory");
            asm volatile("cp.async.wait_group 1;\n" ::: "memory");
        } else {
            asm volatile("cp.async.wait_group 0;\n" ::: "memory");
        }
        __syncthreads();

        const uint32_t* Ahi = smem_u32 + (size_t)cur * 8192;
        const uint32_t* Alo = Ahi + 2048;
        const uint32_t* Bhi = Ahi + 4096;
        const uint32_t* Blo = Ahi + 6144;

        #pragma unroll
        for (int s = 0; s < 2; s++) {
            const int kwb = s * 8;
            uint32_t ah[4][4], al[4][4];
            #pragma unroll
            for (int mi = 0; mi < 4; mi++) {
                int r0 = wm * 64 + mi * 16 + grp;
                ah[mi][0] = lds_frag(Ahi, r0,     kwb + tid4);
                ah[mi][1] = lds_frag(Ahi, r0 + 8, kwb + tid4);
                ah[mi][2] = lds_frag(Ahi, r0,     kwb + tid4 + 4);
                ah[mi][3] = lds_frag(Ahi, r0 + 8, kwb + tid4 + 4);
                al[mi][0] = lds_frag(Alo, r0,     kwb + tid4);
                al[mi][1] = lds_frag(Alo, r0 + 8, kwb + tid4);
                al[mi][2] = lds_frag(Alo, r0,     kwb + tid4 + 4);
                al[mi][3] = lds_frag(Alo, r0 + 8, kwb + tid4 + 4);
            }
            uint32_t bh[4][2], bl[4][2];
            #pragma unroll
            for (int ni = 0; ni < 4; ni++) {
                int r0 = wn * 32 + ni * 8 + grp;
                bh[ni][0] = lds_frag(Bhi, r0, kwb + tid4);
                bh[ni][1] = lds_frag(Bhi, r0, kwb + tid4 + 4);
                bl[ni][0] = lds_frag(Blo, r0, kwb + tid4);
                bl[ni][1] = lds_frag(Blo, r0, kwb + tid4 + 4);
            }
            #pragma unroll
            for (int mi = 0; mi < 4; mi++)
                #pragma unroll
                for (int ni = 0; ni < 4; ni++) {
                    mma_bf16(acc[mi][ni], ah[mi][0], ah[mi][1], ah[mi][2], ah[mi][3],
                             bh[ni][0], bh[ni][1]);
                    mma_bf16(acc[mi][ni], ah[mi][0], ah[mi][1], ah[mi][2], ah[mi][3],
                             bl[ni][0], bl[ni][1]);
                    mma_bf16(acc[mi][ni], al[mi][0], al[mi][1], al[mi][2], al[mi][3],
                             bh[ni][0], bh[ni][1]);
                }
        }
        __syncthreads();
    }

    #pragma unroll
    for (int mi = 0; mi < 4; mi++) {
        int row = wm * 64 + mi * 16 + grp;
        int n  = n0 + row;
        #pragma unroll
        for (int ni = 0; ni < 4; ni++) {
            int oc = wn * 32 + ni * 8 + tid4 * 2;
            float b0v = bout[oc], b1v = bout[oc + 1];
            size_t base0 = ((size_t)b * NN + n) * CC + oc;
            out[base0]     = acc[mi][ni][0] + b0v;
            out[base0 + 1] = acc[mi][ni][1] + b1v;
            size_t base1 = ((size_t)b * NN + n + 8) * CC + oc;
            out[base1]     = acc[mi][ni][2] + b0v;
            out[base1 + 1] = acc[mi][ni][3] + b1v;
        }
    }
}

// ---------------- launch ----------------
extern "C" void kernel_launch(void* const* d_in, const int* in_sizes, int n_in,
                              void* d_out, int out_size) {
    const float* x     = (const float*)d_in[0];
    const float* Wfx   = (const float*)d_in[1];
    const float* bfx   = (const float*)d_in[2];
    const float* Wx    = (const float*)d_in[3];
    const float* bx    = (const float*)d_in[4];
    const float* Wsl   = (const float*)d_in[5];
    const float* bsl   = (const float*)d_in[6];
    const float* temp  = (const float*)d_in[7];
    const float* Wq    = (const float*)d_in[8];
    const float* Wk    = (const float*)d_in[9];
    const float* Wv    = (const float*)d_in[10];
    const float* Wout  = (const float*)d_in[11];
    const float* bout  = (const float*)d_in[12];
    float* out = (float*)d_out;

    float *p_fx, *p_tokp, *p_normp, *p_tok, *p_norm, *p_lb;
    __nv_bfloat16 *p_xhi, *p_xlo, *p_whi, *p_wlo;
    __nv_bfloat16 *p_swhi, *p_swlo, *p_Mthi, *p_Mtlo;
    cudaGetSymbolAddress((void**)&p_fx, g_fx);
    cudaGetSymbolAddress((void**)&p_tokp, g_tokp);
    cudaGetSymbolAddress((void**)&p_normp, g_normp);
    cudaGetSymbolAddress((void**)&p_tok, g_tok);
    cudaGetSymbolAddress((void**)&p_norm, g_norm);
    cudaGetSymbolAddress((void**)&p_lb, g_lbias);
    cudaGetSymbolAddress((void**)&p_xhi, g_xhi);
    cudaGetSymbolAddress((void**)&p_xlo, g_xlo);
    cudaGetSymbolAddress((void**)&p_whi, g_whi);
    cudaGetSymbolAddress((void**)&p_wlo, g_wlo);
    cudaGetSymbolAddress((void**)&p_swhi, g_swhi);
    cudaGetSymbolAddress((void**)&p_swlo, g_swlo);
    cudaGetSymbolAddress((void**)&p_Mthi, g_Mthi);
    cudaGetSymbolAddress((void**)&p_Mtlo, g_Mtlo);

    static bool attr_set = false;
    if (!attr_set) {
        cudaFuncSetAttribute(conv_mma_kernel,
                             cudaFuncAttributeMaxDynamicSharedMemorySize, 2 * CSTAGE);
        cudaFuncSetAttribute(final_mma_kernel,
                             cudaFuncAttributeMaxDynamicSharedMemorySize, 65536);
        attr_set = true;
    }

    dim3 blk(16, 16);

    // 0. staging: x split, fx weights split, combined logit weights, logit bias
    split_x_kernel<<<(BB * NN * CC) / 256, 256>>>(x, p_xhi, p_xlo);
    split_w_kernel<<<(512 * KTOT) / 256, 256>>>(Wfx, p_whi, p_wlo);
    combine_w_kernel<<<dim3(512, 9), 128>>>(Wx, Wsl, temp, p_whi, p_wlo);
    lbias_kernel<<<512, 32>>>(bx, Wsl, bsl, temp, p_lb);

    // 1. fused conv (128x256 tiles, ldmatrix): fx (ocb 0-1) + softmax (ocb 2-3)
    conv_mma_kernel<<<dim3(4, 512, BB), 256, 2 * CSTAGE>>>(
        p_xhi, p_xlo, p_whi, p_wlo, bfx, p_lb, p_fx, p_swhi, p_swlo);

    // 2. slice token split-K partials + reduce
    token_reduce_kernel<<<dim3(SPLITS, BB * HEADS), blk>>>(
        p_swhi, p_swlo, p_fx, p_tokp, p_normp);
    split_reduce_kernel<<<260, 256>>>(p_tokp, p_normp, p_tok, p_norm);

    // 3. tiny attention + fused Wout fold -> Mt (bf16 hi/lo)
    attn_kernel<<<BB * HEADS, blk>>>(p_tok, p_norm, Wq, Wk, Wv, Wout, p_Mthi, p_Mtlo);

    // 4. fused scatter + projection on tensor cores
    final_mma_kernel<<<1024, 256, 65536>>>(p_swhi, p_swlo, p_Mthi, p_Mtlo, bout, out);
}

// round 7
// speedup vs baseline: 3.3018x; 1.0189x over previous
#include <cuda_runtime.h>
#include <cuda_bf16.h>
#include <math.h>
#include <stdint.h>

// Problem constants
#define BB 2
#define HH 256
#define WW 256
#define NN 65536          // H*W
#define CC 128
#define HEADS 8
#define DH 64             // dim_head
#define GG 64             // SLICE
#define INNER 512         // HEADS*DH
#define SPLITS 64         // split-K for token reduction
#define CHUNK 1024        // tokens per split (NN/SPLITS)
#define KTOT 1152         // 9 taps * 128 channels

// ---------------- device scratch (static, no allocs) ----------------
__device__ float g_fx[(size_t)BB * NN * INNER];      // fx_mid  [b][n][inner]
__device__ float g_tokp[(size_t)SPLITS * BB * HEADS * GG * DH];
__device__ float g_normp[(size_t)SPLITS * BB * HEADS * GG];
__device__ float g_tok [(size_t)BB * HEADS * GG * DH];
__device__ float g_norm[(size_t)BB * HEADS * GG];
__device__ float g_lbias[INNER];                     // (bx·Wslice + bslice)/temp

// slice weights as bf16 hi/lo pair  [bh][n][g]
__device__ __align__(16) __nv_bfloat16 g_swhi[(size_t)BB * HEADS * NN * GG];
__device__ __align__(16) __nv_bfloat16 g_swlo[(size_t)BB * HEADS * NN * GG];
// Mt = (out_slice · Wout^T) transposed: [b][o][h*64+g], bf16 hi/lo
__device__ __align__(16) __nv_bfloat16 g_Mthi[(size_t)BB * CC * INNER];
__device__ __align__(16) __nv_bfloat16 g_Mtlo[(size_t)BB * CC * INNER];

// bf16 3-split staging for conv
__device__ __align__(16) __nv_bfloat16 g_xhi[(size_t)BB * NN * CC];
__device__ __align__(16) __nv_bfloat16 g_xlo[(size_t)BB * NN * CC];
// rows 0..511: Wfx cols; rows 512..1023: combined logit weights (Wx·Wslice/temp)
__device__ __align__(16) __nv_bfloat16 g_whi[(size_t)1024 * KTOT];
__device__ __align__(16) __nv_bfloat16 g_wlo[(size_t)1024 * KTOT];

// ---------------- prep kernels ----------------
__global__ void split_x_kernel(const float* __restrict__ x,
                               __nv_bfloat16* __restrict__ xhi,
                               __nv_bfloat16* __restrict__ xlo) {
    size_t i = (size_t)blockIdx.x * 256 + threadIdx.x;
    float f = x[i];
    __nv_bfloat16 h = __float2bfloat16(f);
    float r = f - __bfloat162float(h);
    xhi[i] = h;
    xlo[i] = __float2bfloat16(r);
}

// Wfx (fx conv weights) -> rows 0..511 of g_whi/g_wlo, transposed [oc][k]
__global__ void split_w_kernel(const float* __restrict__ Wfx,
                               __nv_bfloat16* __restrict__ whi,
                               __nv_bfloat16* __restrict__ wlo) {
    int i = blockIdx.x * 256 + threadIdx.x;   // 512*1152 total
    int oc = i / KTOT;
    int k  = i - oc * KTOT;
    float f = Wfx[(size_t)k * 512 + oc];
    __nv_bfloat16 h = __float2bfloat16(f);
    float r = f - __bfloat162float(h);
    whi[i] = h;
    wlo[i] = __float2bfloat16(r);
}

// W~[k][h*64+g] = (sum_d Wx[k][h*64+d]*Wslice[g][d]) / temp_h -> rows 512..1023
__global__ void combine_w_kernel(const float* __restrict__ Wx,
                                 const float* __restrict__ Wsl,
                                 const float* __restrict__ temp,
                                 __nv_bfloat16* __restrict__ whi,
                                 __nv_bfloat16* __restrict__ wlo) {
    __shared__ float ws[64];
    const int col = blockIdx.x;          // 0..511
    const int h = col >> 6, g = col & 63;
    const int tid = threadIdx.x;         // 128
    if (tid < 64) ws[tid] = Wsl[g * 64 + tid];
    __syncthreads();
    float t = fminf(fmaxf(temp[h], 0.1f), 5.0f);
    float invt = 1.0f / t;
    int k = blockIdx.y * 128 + tid;      // 9 y-blocks -> 0..1151
    const float* wr = Wx + (size_t)k * 512 + h * 64;
    float s = 0.f;
    #pragma unroll 8
    for (int d = 0; d < 64; d++) s += wr[d] * ws[d];
    s *= invt;
    __nv_bfloat16 hv = __float2bfloat16(s);
    size_t o = (size_t)(512 + col) * KTOT + k;
    whi[o] = hv;
    wlo[o] = __float2bfloat16(s - __bfloat162float(hv));
}

// lbias[h*64+g] = (bx_h · Wslice_g + bslice_g) / temp_h   (one block per col)
__global__ void lbias_kernel(const float* __restrict__ bx,
                             const float* __restrict__ Wsl,
                             const float* __restrict__ bsl,
                             const float* __restrict__ temp,
                             float* __restrict__ lb) {
    int col = blockIdx.x;                // 0..511
    int h = col >> 6, g = col & 63;
    int lane = threadIdx.x;              // 32
    float s = bx[h * 64 + lane] * Wsl[g * 64 + lane]
            + bx[h * 64 + 32 + lane] * Wsl[g * 64 + 32 + lane];
    #pragma unroll
    for (int o = 16; o > 0; o >>= 1)
        s += __shfl_xor_sync(0xffffffffu, s, o);
    if (lane == 0) {
        float t = fminf(fmaxf(temp[h], 0.1f), 5.0f);
        lb[col] = (s + bsl[g]) / t;
    }
}

// ---------------- shared MMA plumbing ----------------
__device__ __forceinline__ void cp16(uint32_t saddr, const void* g, bool valid) {
    int sz = valid ? 16 : 0;
    asm volatile("cp.async.cg.shared.global [%0], [%1], 16, %2;\n"
                 :: "r"(saddr), "l"(g), "r"(sz));
}

// 16-word rows (final kernel, kc=32 layout)
__device__ __forceinline__ uint32_t lds_frag(const uint32_t* base, int row, int kw) {
    return base[row * 16 + ((((kw >> 2) ^ (row & 3)) << 2) | (kw & 3))];
}

__device__ __forceinline__ void mma_bf16(float c[4], uint32_t a0, uint32_t a1,
                                         uint32_t a2, uint32_t a3,
                                         uint32_t b0, uint32_t b1) {
    asm volatile(
        "mma.sync.aligned.m16n8k16.row.col.f32.bf16.bf16.f32 "
        "{%0,%1,%2,%3}, {%4,%5,%6,%7}, {%8,%9}, {%0,%1,%2,%3};"
        : "+f"(c[0]), "+f"(c[1]), "+f"(c[2]), "+f"(c[3])
        : "r"(a0), "r"(a1), "r"(a2), "r"(a3), "r"(b0), "r"(b1));
}

__device__ __forceinline__ void ldsm4(uint32_t r[4], uint32_t addr) {
    asm volatile("ldmatrix.sync.aligned.m8n8.x4.shared.b16 {%0,%1,%2,%3}, [%4];"
                 : "=r"(r[0]), "=r"(r[1]), "=r"(r[2]), "=r"(r[3]) : "r"(addr));
}

// ---------------- conv: implicit GEMM 128x256, kc=64, ldmatrix feed ----------------
// ocb 0..1: fx output (cols ocb*256..+255); ocb 2..3: slice-weight softmax (4 heads each).
// Stage (96KB): Ahi 16K | Alo 16K | Bhi 32K | Blo 32K.
// Rows are 128B (64 bf16), granule-swizzled: off = row*128 + ((gr ^ (row&7))<<4).
#define CSTAGE 98304

__device__ __forceinline__ void conv_load(
    uint32_t st,
    const __nv_bfloat16* __restrict__ Xhi, const __nv_bfloat16* __restrict__ Xlo,
    const __nv_bfloat16* __restrict__ Whi, const __nv_bfloat16* __restrict__ Wlo,
    int it, int b, int hrow, int w0, int ocb, int tid)
{
    const int kg  = it * 64;
    const int tap = kg >> 7;
    const int dy = tap / 3 - 1, dx = tap % 3 - 1;
    const int c0 = kg & 127;            // 0 or 64
    const int hp = hrow + dy;
    const bool hok = (hp >= 0) && (hp < HH);
    const int hpc = hok ? hp : 0;

    // A: 2 arrays x 128 rows x 8 granules = 2048 lines (j = 0..7)
    #pragma unroll
    for (int j = 0; j < 8; j++) {
        int id  = tid + j * 256;
        int arr = id >> 10;             // 0:Ahi 1:Alo
        int l   = id & 1023;
        int row = l >> 3;
        int gr  = l & 7;
        uint32_t saddr = st + arr * 16384 + row * 128 + ((gr ^ (row & 7)) << 4);
        int wp = w0 + row + dx;
        bool valid = hok && (wp >= 0) && (wp < WW);
        int wpc = valid ? wp : 0;
        const __nv_bfloat16* g = (arr == 0 ? Xhi : Xlo) +
            (((size_t)b * NN + (size_t)hpc * WW + wpc) * CC + c0 + gr * 8);
        cp16(saddr, g, valid);
    }
    // B: 2 arrays x 256 rows x 8 granules = 4096 lines (j = 8..23)
    #pragma unroll
    for (int j = 8; j < 24; j++) {
        int id  = tid + (j - 8) * 256;  // 0..4095
        int arr = id >> 11;             // 0:Bhi 1:Blo
        int l   = id & 2047;
        int row = l >> 3;
        int gr  = l & 7;
        uint32_t saddr = st + 32768 + arr * 32768 + row * 128 + ((gr ^ (row & 7)) << 4);
        const __nv_bfloat16* g = (arr == 0 ? Whi : Wlo) +
            ((size_t)(ocb * 256 + row) * KTOT + kg + gr * 8);
        cp16(saddr, g, true);
    }
}

__global__ __launch_bounds__(256, 1)
void conv_mma_kernel(const __nv_bfloat16* __restrict__ Xhi,
                     const __nv_bfloat16* __restrict__ Xlo,
                     const __nv_bfloat16* __restrict__ Whi,
                     const __nv_bfloat16* __restrict__ Wlo,
                     const float* __restrict__ bfx,
                     const float* __restrict__ lbias,
                     float* __restrict__ ofx,
                     __nv_bfloat16* __restrict__ swhi,
                     __nv_bfloat16* __restrict__ swlo)
{
    extern __shared__ char smem[];           // 2 stages x 96KB

    const int ocb = blockIdx.x;              // 0..3
    const int pt  = blockIdx.y;              // 0..511
    const int b   = blockIdx.z;
    const int n0  = pt * 128;
    const int hrow = n0 >> 8;
    const int w0   = n0 & 255;

    const int tid  = threadIdx.x;
    const int wid  = tid >> 5;
    const int lane = tid & 31;
    const int grp  = lane >> 2;
    const int tid4 = lane & 3;
    const int wm   = wid & 1;                // 2 row-groups of 64
    const int wn   = wid >> 1;               // 4 col-groups of 64

    // ldmatrix lane addressing precompute
    const int t8   = lane >> 3;              // tile index 0..3
    const int r8   = lane & 7;               // row within tile
    const int a_roff = ((t8 & 1) << 3) + r8; // A: +0/+8 rows, granule pair t8>>1
    const int a_gsel = t8 >> 1;
    const int b_roff = ((t8 >> 1) << 3) + r8;// B: +0/+8 rows, granule pair t8&1
    const int b_gsel = t8 & 1;

    float acc[4][8][4];
    #pragma unroll
    for (int i = 0; i < 4; i++)
        #pragma unroll
        for (int j = 0; j < 8; j++)
            #pragma unroll
            for (int r = 0; r < 4; r++) acc[i][j][r] = 0.f;

    uint32_t sbase = (uint32_t)__cvta_generic_to_shared(smem);

    conv_load(sbase, Xhi, Xlo, Whi, Wlo, 0, b, hrow, w0, ocb, tid);
    asm volatile("cp.async.commit_group;\n" ::: "memory");

    for (int it = 0; it < 18; ++it) {
        const int cur = it & 1;
        if (it + 1 < 18) {
            conv_load(sbase + (uint32_t)(1 - cur) * CSTAGE,
                      Xhi, Xlo, Whi, Wlo, it + 1, b, hrow, w0, ocb, tid);
            asm volatile("cp.async.commit_group;\n" ::: "memory");
            asm volatile("cp.async.wait_group 1;\n" ::: "memory");
        } else {
            asm volatile("cp.async.wait_group 0;\n" ::: "memory");
        }
        __syncthreads();

        const uint32_t stA = sbase + (uint32_t)cur * CSTAGE;
        const uint32_t stB = stA + 32768;

        #pragma unroll
        for (int s = 0; s < 4; s++) {
            // A fragments: 4 mi x (hi, lo)
            uint32_t ah[4][4], al[4][4];
            #pragma unroll
            for (int mi = 0; mi < 4; mi++) {
                int row = wm * 64 + mi * 16 + a_roff;
                int g = 2 * s + a_gsel;
                uint32_t addr = stA + row * 128 + ((g ^ (row & 7)) << 4);
                ldsm4(ah[mi], addr);
                ldsm4(al[mi], addr + 16384);
            }
            // B fragments per 16-col pair; term-major MMA order to avoid
            // same-accumulator RAW chains (gap of 8 independent MMAs).
            #pragma unroll
            for (int np = 0; np < 4; np++) {
                int row = wn * 64 + np * 16 + b_roff;
                int g = 2 * s + b_gsel;
                uint32_t addr = stB + row * 128 + ((g ^ (row & 7)) << 4);
                uint32_t bh[4], bl[4];
                ldsm4(bh, addr);
                ldsm4(bl, addr + 32768);
                // term 1: A_hi * B_hi
                #pragma unroll
                for (int mi = 0; mi < 4; mi++) {
                    mma_bf16(acc[mi][2 * np],     ah[mi][0], ah[mi][1], ah[mi][2], ah[mi][3], bh[0], bh[1]);
                    mma_bf16(acc[mi][2 * np + 1], ah[mi][0], ah[mi][1], ah[mi][2], ah[mi][3], bh[2], bh[3]);
                }
                // term 2: A_hi * B_lo
                #pragma unroll
                for (int mi = 0; mi < 4; mi++) {
                    mma_bf16(acc[mi][2 * np],     ah[mi][0], ah[mi][1], ah[mi][2], ah[mi][3], bl[0], bl[1]);
                    mma_bf16(acc[mi][2 * np + 1], ah[mi][0], ah[mi][1], ah[mi][2], ah[mi][3], bl[2], bl[3]);
                }
                // term 3: A_lo * B_hi
                #pragma unroll
                for (int mi = 0; mi < 4; mi++) {
                    mma_bf16(acc[mi][2 * np],     al[mi][0], al[mi][1], al[mi][2], al[mi][3], bh[0], bh[1]);
                    mma_bf16(acc[mi][2 * np + 1], al[mi][0], al[mi][1], al[mi][2], al[mi][3], bh[2], bh[3]);
                }
            }
        }
        __syncthreads();
    }

    if (ocb < 2) {
        // fx output: direct fp32 stores with bias
        const int ocbase = ocb * 256;
        #pragma unroll
        for (int mi = 0; mi < 4; mi++) {
            int row = wm * 64 + mi * 16 + grp;
            int n  = n0 + row;
            #pragma unroll
            for (int ni = 0; ni < 8; ni++) {
                int col = wn * 64 + ni * 8 + tid4 * 2;
                int oc  = ocbase + col;
                float b0v = bfx[oc], b1v = bfx[oc + 1];
                size_t base0 = ((size_t)b * NN + n) * INNER + oc;
                ofx[base0]     = acc[mi][ni][0] + b0v;
                ofx[base0 + 1] = acc[mi][ni][1] + b1v;
                size_t base1 = ((size_t)b * NN + n + 8) * INNER + oc;
                ofx[base1]     = acc[mi][ni][2] + b0v;
                ofx[base1 + 1] = acc[mi][ni][3] + b1v;
            }
        }
    } else {
        // logits: stage to smem, softmax per (pixel, head), emit bf16 hi/lo
        float* sred = (float*)smem;          // [128][260]
        #pragma unroll
        for (int mi = 0; mi < 4; mi++) {
            int row = wm * 64 + mi * 16 + grp;
            #pragma unroll
            for (int ni = 0; ni < 8; ni++) {
                int col = wn * 64 + ni * 8 + tid4 * 2;
                sred[row * 260 + col]           = acc[mi][ni][0];
                sred[row * 260 + col + 1]       = acc[mi][ni][1];
                sred[(row + 8) * 260 + col]     = acc[mi][ni][2];
                sred[(row + 8) * 260 + col + 1] = acc[mi][ni][3];
            }
        }
        __syncthreads();

        #pragma unroll
        for (int pass = 0; pass < 2; pass++) {
            int tsk = tid + pass * 256;      // 0..511
            int row  = tsk >> 2;
            int hloc = tsk & 3;
            int h = (ocb - 2) * 4 + hloc;
            int n = n0 + row;
            const float* lb = lbias + h * 64;
            float* sr = sred + row * 260 + hloc * 64;

            float mx = -1e30f;
            #pragma unroll 8
            for (int g = 0; g < 64; g++) mx = fmaxf(mx, sr[g] + lb[g]);
            float ssum = 0.f;
            #pragma unroll 8
            for (int g = 0; g < 64; g++) {
                float e = __expf(sr[g] + lb[g] - mx);
                ssum += e;
                sr[g] = e;
            }
            float inv = 1.0f / ssum;

            size_t base = ((size_t)(b * HEADS + h) * NN + n) * GG;
            #pragma unroll
            for (int c = 0; c < 8; c++) {
                union { __nv_bfloat16 hb[8]; uint4 u; } Uh, Ul;
                #pragma unroll
                for (int e = 0; e < 8; e++) {
                    float v = sr[c * 8 + e] * inv;
                    __nv_bfloat16 hv = __float2bfloat16(v);
                    Uh.hb[e] = hv;
                    Ul.hb[e] = __float2bfloat16(v - __bfloat162float(hv));
                }
                ((uint4*)(swhi + base))[c] = Uh.u;
                ((uint4*)(swlo + base))[c] = Ul.u;
            }
        }
    }
}

// ---------------- K3: split-K reduction: slice_token partials ----------------
// 16-token tiles, vectorized loads, 16 independent FFMA accs.
__global__ void token_reduce_kernel(const __nv_bfloat16* __restrict__ whi,
                                    const __nv_bfloat16* __restrict__ wlo,
                                    const float* __restrict__ fx,
                                    float* __restrict__ tokp,
                                    float* __restrict__ normp) {
    const int bh = blockIdx.y;
    const int b = bh >> 3, h = bh & 7;
    const int split = blockIdx.x;
    const int nbase = split * CHUNK;
    const int tx = threadIdx.x, ty = threadIdx.y;
    const int tid = ty * 16 + tx;

    __shared__ float wb[16][64];
    __shared__ float fb[16][64];

    float acc[4][4] = {};
    float nacc[4] = {};

    const int lt = tid >> 4;            // token row 0..15
    const int lq = (tid & 15) * 4;      // col group

    for (int t0 = 0; t0 < CHUNK; t0 += 16) {
        {
            int n = nbase + t0 + lt;
            size_t wi = ((size_t)bh * NN + n) * GG + lq;
            uint2 uh = *(const uint2*)(whi + wi);
            uint2 ul = *(const uint2*)(wlo + wi);
            const __nv_bfloat162* h2 = (const __nv_bfloat162*)&uh;
            const __nv_bfloat162* l2 = (const __nv_bfloat162*)&ul;
            float4 wv;
            wv.x = __bfloat162float(h2[0].x) + __bfloat162float(l2[0].x);
            wv.y = __bfloat162float(h2[0].y) + __bfloat162float(l2[0].y);
            wv.z = __bfloat162float(h2[1].x) + __bfloat162float(l2[1].x);
            wv.w = __bfloat162float(h2[1].y) + __bfloat162float(l2[1].y);
            *(float4*)&wb[lt][lq] = wv;
            *(float4*)&fb[lt][lq] =
                *(const float4*)(fx + ((size_t)b * NN + n) * INNER + h * DH + lq);
        }
        __syncthreads();
        #pragma unroll
        for (int t = 0; t < 16; t++) {
            float a[4], bv[4];
            #pragma unroll
            for (int i = 0; i < 4; i++) a[i] = wb[t][ty + 16 * i];
            #pragma unroll
            for (int j = 0; j < 4; j++) bv[j] = fb[t][tx + 16 * j];
            #pragma unroll
            for (int i = 0; i < 4; i++)
                #pragma unroll
                for (int j = 0; j < 4; j++)
                    acc[i][j] += a[i] * bv[j];
            if (tx == 0) {
                #pragma unroll
                for (int i = 0; i < 4; i++) nacc[i] += a[i];
            }
        }
        __syncthreads();
    }

    const size_t base = ((size_t)split * (BB * HEADS) + bh) * (GG * DH);
    #pragma unroll
    for (int i = 0; i < 4; i++)
        #pragma unroll
        for (int j = 0; j < 4; j++)
            tokp[base + (size_t)(ty + 16 * i) * DH + tx + 16 * j] = acc[i][j];
    if (tx == 0) {
        #pragma unroll
        for (int i = 0; i < 4; i++)
            normp[((size_t)split * (BB * HEADS) + bh) * GG + ty + 16 * i] = nacc[i];
    }
}

// ---------------- K3b: deterministic split reduction ----------------
__global__ void split_reduce_kernel(const float* __restrict__ tokp,
                                    const float* __restrict__ normp,
                                    float* __restrict__ tok,
                                    float* __restrict__ norm) {
    const int blk = blockIdx.x;
    const int tid = threadIdx.x;
    if (blk < 256) {
        int idx = blk * 256 + tid;
        float s = 0.f;
        #pragma unroll 8
        for (int sp = 0; sp < SPLITS; sp++)
            s += tokp[(size_t)sp * 65536 + idx];
        tok[idx] = s;
    } else {
        int idx = (blk - 256) * 256 + tid;
        float s = 0.f;
        #pragma unroll 8
        for (int sp = 0; sp < SPLITS; sp++)
            s += normp[(size_t)sp * 1024 + idx];
        norm[idx] = s;
    }
}

// ---------------- K4: tiny attention per (b,h), emits Mt bf16 hi/lo ----------------
__global__ void attn_kernel(const float* __restrict__ tok,
                            const float* __restrict__ norm,
                            const float* __restrict__ Wq,
                            const float* __restrict__ Wk,
                            const float* __restrict__ Wv,
                            const float* __restrict__ Wout,
                            __nv_bfloat16* __restrict__ Mthi,
                            __nv_bfloat16* __restrict__ Mtlo) {
    const int bh = blockIdx.x;
    const int b = bh >> 3, h = bh & 7;
    const int tx = threadIdx.x, ty = threadIdx.y;
    const int tid = ty * 16 + tx;

    __shared__ float A[64][65];
    __shared__ float Bm[64][65];
    __shared__ float Cm[64][65];

    #pragma unroll
    for (int e = 0; e < 16; e++) {
        int idx = tid + e * 256;
        int g = idx >> 6, d = idx & 63;
        A[g][d] = tok[(size_t)bh * 4096 + idx] / (norm[bh * 64 + g] + 1e-5f);
    }
    __syncthreads();

    {
        float aq[4][4] = {}, ak[4][4] = {};
        #pragma unroll
        for (int kk = 0; kk < 64; kk++) {
            float a[4];
            #pragma unroll
            for (int i = 0; i < 4; i++) a[i] = A[ty + 16 * i][kk];
            #pragma unroll
            for (int j = 0; j < 4; j++) {
                float wq = __ldg(&Wq[(tx + 16 * j) * 64 + kk]);
                float wk = __ldg(&Wk[(tx + 16 * j) * 64 + kk]);
                #pragma unroll
                for (int i = 0; i < 4; i++) {
                    aq[i][j] += a[i] * wq;
                    ak[i][j] += a[i] * wk;
                }
            }
        }
        #pragma unroll
        for (int i = 0; i < 4; i++)
            #pragma unroll
            for (int j = 0; j < 4; j++) {
                Bm[ty + 16 * i][tx + 16 * j] = aq[i][j];
                Cm[ty + 16 * i][tx + 16 * j] = ak[i][j];
            }
    }
    __syncthreads();

    {
        float L[4][4] = {};
        #pragma unroll
        for (int kk = 0; kk < 64; kk++) {
            float a[4], bv[4];
            #pragma unroll
            for (int i = 0; i < 4; i++) a[i] = Bm[ty + 16 * i][kk];
            #pragma unroll
            for (int j = 0; j < 4; j++) bv[j] = Cm[tx + 16 * j][kk];
            #pragma unroll
            for (int i = 0; i < 4; i++)
                #pragma unroll
                for (int j = 0; j < 4; j++)
                    L[i][j] += a[i] * bv[j];
        }
        #pragma unroll
        for (int i = 0; i < 4; i++) {
            #pragma unroll
            for (int j = 0; j < 4; j++) L[i][j] *= 0.125f;
            float mx = L[i][0];
            #pragma unroll
            for (int j = 1; j < 4; j++) mx = fmaxf(mx, L[i][j]);
            #pragma unroll
            for (int o = 1; o < 16; o <<= 1)
                mx = fmaxf(mx, __shfl_xor_sync(0xffffffffu, mx, o, 16));
            float s = 0.f;
            #pragma unroll
            for (int j = 0; j < 4; j++) { L[i][j] = __expf(L[i][j] - mx); s += L[i][j]; }
            #pragma unroll
            for (int o = 1; o < 16; o <<= 1)
                s += __shfl_xor_sync(0xffffffffu, s, o, 16);
            float inv = 1.0f / s;
            #pragma unroll
            for (int j = 0; j < 4; j++)
                A[ty + 16 * i][tx + 16 * j] = L[i][j] * inv;
        }
    }
    __syncthreads();

    #pragma unroll
    for (int e = 0; e < 16; e++) {
        int idx = tid + e * 256;
        int g = idx >> 6;
        Bm[g][idx & 63] = tok[(size_t)bh * 4096 + idx] / (norm[bh * 64 + g] + 1e-5f);
    }
    __syncthreads();

    {
        float av[4][4] = {};
        #pragma unroll
        for (int kk = 0; kk < 64; kk++) {
            float a[4];
            #pragma unroll
            for (int i = 0; i < 4; i++) a[i] = Bm[ty + 16 * i][kk];
            #pragma unroll
            for (int j = 0; j < 4; j++) {
                float wv = __ldg(&Wv[(tx + 16 * j) * 64 + kk]);
                #pragma unroll
                for (int i = 0; i < 4; i++) av[i][j] += a[i] * wv;
            }
        }
        __syncthreads();
        #pragma unroll
        for (int i = 0; i < 4; i++)
            #pragma unroll
            for (int j = 0; j < 4; j++)
                Cm[ty + 16 * i][tx + 16 * j] = av[i][j];
    }
    __syncthreads();

    {
        float ao[4][4] = {};
        #pragma unroll
        for (int kk = 0; kk < 64; kk++) {
            float a[4], bv[4];
            #pragma unroll
            for (int i = 0; i < 4; i++) a[i] = A[ty + 16 * i][kk];
            #pragma unroll
            for (int j = 0; j < 4; j++) bv[j] = Cm[kk][tx + 16 * j];
            #pragma unroll
            for (int i = 0; i < 4; i++)
                #pragma unroll
                for (int j = 0; j < 4; j++)
                    ao[i][j] += a[i] * bv[j];
        }
        __syncthreads();
        #pragma unroll
        for (int i = 0; i < 4; i++)
            #pragma unroll
            for (int j = 0; j < 4; j++)
                Bm[ty + 16 * i][tx + 16 * j] = ao[i][j];
    }
    __syncthreads();

    {
        float am[4][8] = {};
        #pragma unroll
        for (int kk = 0; kk < 64; kk++) {
            float a[4];
            #pragma unroll
            for (int i = 0; i < 4; i++) a[i] = Bm[ty + 16 * i][kk];
            #pragma unroll
            for (int j = 0; j < 8; j++) {
                float wv = __ldg(&Wout[(size_t)(tx + 16 * j) * INNER + h * DH + kk]);
                #pragma unroll
                for (int i = 0; i < 4; i++) am[i][j] += a[i] * wv;
            }
        }
        #pragma unroll
        for (int i = 0; i < 4; i++) {
            int g = ty + 16 * i;
            #pragma unroll
            for (int j = 0; j < 8; j++) {
                int o = tx + 16 * j;
                float v = am[i][j];
                __nv_bfloat16 hv = __float2bfloat16(v);
                float r = v - __bfloat162float(hv);
                size_t idx = ((size_t)b * CC + o) * INNER + h * DH + g;
                Mthi[idx] = hv;
                Mtlo[idx] = __float2bfloat16(r);
            }
        }
    }
}

// ---------------- K5: fused scatter + projection on tensor cores ----------------
__global__ __launch_bounds__(256)
void final_mma_kernel(const __nv_bfloat16* __restrict__ Whi,
                      const __nv_bfloat16* __restrict__ Wlo,
                      const __nv_bfloat16* __restrict__ Mthi,
                      const __nv_bfloat16* __restrict__ Mtlo,
                      const float* __restrict__ bout,
                      float* __restrict__ out)
{
    extern __shared__ uint32_t smem_u32[];

    const int pt = blockIdx.x;
    const int b  = pt >> 9;
    const int n0 = (pt & 511) * 128;

    const int tid  = threadIdx.x;
    const int wid  = tid >> 5;
    const int lane = tid & 31;
    const int grp  = lane >> 2;
    const int tid4 = lane & 3;
    const int wm   = wid & 1;
    const int wn   = wid >> 1;

    float acc[4][4][4];
    #pragma unroll
    for (int i = 0; i < 4; i++)
        #pragma unroll
        for (int j = 0; j < 4; j++)
            #pragma unroll
            for (int r = 0; r < 4; r++) acc[i][j][r] = 0.f;

    uint32_t sbase = (uint32_t)__cvta_generic_to_shared(smem_u32);

    auto load_fin = [&](uint32_t sb, int it) {
        const int h  = it >> 1;
        const int g0 = (it & 1) * 32;
        #pragma unroll
        for (int j = 0; j < 8; j++) {
            int id  = tid + j * 256;
            int arr = id >> 9;
            int c   = id & 511;
            int row = c >> 2;
            int c4  = c & 3;
            uint32_t woff = (uint32_t)row * 16 + ((c4 ^ (row & 3)) << 2);
            uint32_t saddr = sb + (arr * 2048 + woff) * 4;
            const __nv_bfloat16* g;
            if (arr < 2) {
                size_t off = (((size_t)(b * HEADS + h) * NN) + n0 + row) * GG + g0 + c4 * 8;
                g = (arr == 0 ? Whi : Wlo) + off;
            } else {
                size_t off = ((size_t)b * CC + row) * INNER + h * DH + g0 + c4 * 8;
                g = (arr == 2 ? Mthi : Mtlo) + off;
            }
            cp16(saddr, g, true);
        }
    };

    load_fin(sbase, 0);
    asm volatile("cp.async.commit_group;\n" ::: "memory");

    for (int it = 0; it < 16; ++it) {
        const int cur = it & 1;
        if (it + 1 < 16) {
            load_fin(sbase + (uint32_t)(1 - cur) * 32768, it + 1);
            asm volatile("cp.async.commit_group;\n" ::: "memory");
            asm volatile("cp.async.wait_group 1;\n" ::: "memory");
        } else {
            asm volatile("cp.async.wait_group 0;\n" ::: "memory");
        }
        __syncthreads();

        const uint32_t* Ahi = smem_u32 + (size_t)cur * 8192;
        const uint32_t* Alo = Ahi + 2048;
        const uint32_t* Bhi = Ahi + 4096;
        const uint32_t* Blo = Ahi + 6144;

        #pragma unroll
        for (int s = 0; s < 2; s++) {
            const int kwb = s * 8;
            uint32_t ah[4][4], al[4][4];
            #pragma unroll
            for (int mi = 0; mi < 4; mi++) {
                int r0 = wm * 64 + mi * 16 + grp;
                ah[mi][0] = lds_frag(Ahi, r0,     kwb + tid4);
                ah[mi][1] = lds_frag(Ahi, r0 + 8, kwb + tid4);
                ah[mi][2] = lds_frag(Ahi, r0,     kwb + tid4 + 4);
                ah[mi][3] = lds_frag(Ahi, r0 + 8, kwb + tid4 + 4);
                al[mi][0] = lds_frag(Alo, r0,     kwb + tid4);
                al[mi][1] = lds_frag(Alo, r0 + 8, kwb + tid4);
                al[mi][2] = lds_frag(Alo, r0,     kwb + tid4 + 4);
                al[mi][3] = lds_frag(Alo, r0 + 8, kwb + tid4 + 4);
            }
            uint32_t bh[4][2], bl[4][2];
            #pragma unroll
            for (int ni = 0; ni < 4; ni++) {
                int r0 = wn * 32 + ni * 8 + grp;
                bh[ni][0] = lds_frag(Bhi, r0, kwb + tid4);
                bh[ni][1] = lds_frag(Bhi, r0, kwb + tid4 + 4);
                bl[ni][0] = lds_frag(Blo, r0, kwb + tid4);
                bl[ni][1] = lds_frag(Blo, r0, kwb + tid4 + 4);
            }
            // term-major: 16-acc gap between same-acc MMAs
            #pragma unroll
            for (int mi = 0; mi < 4; mi++)
                #pragma unroll
                for (int ni = 0; ni < 4; ni++)
                    mma_bf16(acc[mi][ni], ah[mi][0], ah[mi][1], ah[mi][2], ah[mi][3],
                             bh[ni][0], bh[ni][1]);
            #pragma unroll
            for (int mi = 0; mi < 4; mi++)
                #pragma unroll
                for (int ni = 0; ni < 4; ni++)
                    mma_bf16(acc[mi][ni], ah[mi][0], ah[mi][1], ah[mi][2], ah[mi][3],
                             bl[ni][0], bl[ni][1]);
            #pragma unroll
            for (int mi = 0; mi < 4; mi++)
                #pragma unroll
                for (int ni = 0; ni < 4; ni++)
                    mma_bf16(acc[mi][ni], al[mi][0], al[mi][1], al[mi][2], al[mi][3],
                             bh[ni][0], bh[ni][1]);
        }
        __syncthreads();
    }

    #pragma unroll
    for (int mi = 0; mi < 4; mi++) {
        int row = wm * 64 + mi * 16 + grp;
        int n  = n0 + row;
        #pragma unroll
        for (int ni = 0; ni < 4; ni++) {
            int oc = wn * 32 + ni * 8 + tid4 * 2;
            float b0v = bout[oc], b1v = bout[oc + 1];
            size_t base0 = ((size_t)b * NN + n) * CC + oc;
            out[base0]     = acc[mi][ni][0] + b0v;
            out[base0 + 1] = acc[mi][ni][1] + b1v;
            size_t base1 = ((size_t)b * NN + n + 8) * CC + oc;
            out[base1]     = acc[mi][ni][2] + b0v;
            out[base1 + 1] = acc[mi][ni][3] + b1v;
        }
    }
}

// ---------------- launch ----------------
extern "C" void kernel_launch(void* const* d_in, const int* in_sizes, int n_in,
                              void* d_out, int out_size) {
    const float* x     = (const float*)d_in[0];
    const float* Wfx   = (const float*)d_in[1];
    const float* bfx   = (const float*)d_in[2];
    const float* Wx    = (const float*)d_in[3];
    const float* bx    = (const float*)d_in[4];
    const float* Wsl   = (const float*)d_in[5];
    const float* bsl   = (const float*)d_in[6];
    const float* temp  = (const float*)d_in[7];
    const float* Wq    = (const float*)d_in[8];
    const float* Wk    = (const float*)d_in[9];
    const float* Wv    = (const float*)d_in[10];
    const float* Wout  = (const float*)d_in[11];
    const float* bout  = (const float*)d_in[12];
    float* out = (float*)d_out;

    float *p_fx, *p_tokp, *p_normp, *p_tok, *p_norm, *p_lb;
    __nv_bfloat16 *p_xhi, *p_xlo, *p_whi, *p_wlo;
    __nv_bfloat16 *p_swhi, *p_swlo, *p_Mthi, *p_Mtlo;
    cudaGetSymbolAddress((void**)&p_fx, g_fx);
    cudaGetSymbolAddress((void**)&p_tokp, g_tokp);
    cudaGetSymbolAddress((void**)&p_normp, g_normp);
    cudaGetSymbolAddress((void**)&p_tok, g_tok);
    cudaGetSymbolAddress((void**)&p_norm, g_norm);
    cudaGetSymbolAddress((void**)&p_lb, g_lbias);
    cudaGetSymbolAddress((void**)&p_xhi, g_xhi);
    cudaGetSymbolAddress((void**)&p_xlo, g_xlo);
    cudaGetSymbolAddress((void**)&p_whi, g_whi);
    cudaGetSymbolAddress((void**)&p_wlo, g_wlo);
    cudaGetSymbolAddress((void**)&p_swhi, g_swhi);
    cudaGetSymbolAddress((void**)&p_swlo, g_swlo);
    cudaGetSymbolAddress((void**)&p_Mthi, g_Mthi);
    cudaGetSymbolAddress((void**)&p_Mtlo, g_Mtlo);

    static bool attr_set = false;
    if (!attr_set) {
        cudaFuncSetAttribute(conv_mma_kernel,
                             cudaFuncAttributeMaxDynamicSharedMemorySize, 2 * CSTAGE);
        cudaFuncSetAttribute(final_mma_kernel,
                             cudaFuncAttributeMaxDynamicSharedMemorySize, 65536);
        attr_set = true;
    }

    dim3 blk(16, 16);

    // 0. staging: x split, fx weights split, combined logit weights, logit bias
    split_x_kernel<<<(BB * NN * CC) / 256, 256>>>(x, p_xhi, p_xlo);
    split_w_kernel<<<(512 * KTOT) / 256, 256>>>(Wfx, p_whi, p_wlo);
    combine_w_kernel<<<dim3(512, 9), 128>>>(Wx, Wsl, temp, p_whi, p_wlo);
    lbias_kernel<<<512, 32>>>(bx, Wsl, bsl, temp, p_lb);

    // 1. fused conv (128x256 tiles, ldmatrix, term-major MMA order)
    conv_mma_kernel<<<dim3(4, 512, BB), 256, 2 * CSTAGE>>>(
        p_xhi, p_xlo, p_whi, p_wlo, bfx, p_lb, p_fx, p_swhi, p_swlo);

    // 2. slice token split-K partials + reduce
    token_reduce_kernel<<<dim3(SPLITS, BB * HEADS), blk>>>(
        p_swhi, p_swlo, p_fx, p_tokp, p_normp);
    split_reduce_kernel<<<260, 256>>>(p_tokp, p_normp, p_tok, p_norm);

    // 3. tiny attention + fused Wout fold -> Mt (bf16 hi/lo)
    attn_kernel<<<BB * HEADS, blk>>>(p_tok, p_norm, Wq, Wk, Wv, Wout, p_Mthi, p_Mtlo);

    // 4. fused scatter + projection on tensor cores
    final_mma_kernel<<<1024, 256, 65536>>>(p_swhi, p_swlo, p_Mthi, p_Mtlo, bout, out);
}